// round 9
// baseline (speedup 1.0000x reference)
#include <cuda_runtime.h>
#include <cuda_bf16.h>
#include <cstdint>
#include <cstddef>

#define BB 2
#define NNODE 2048
#define DDIM 256
#define HH 8
#define HDIM 32
#define EEDGE 65536
#define KTOP 1024
#define NWRD (NNODE/32)   // 64 u32 words per adjacency row

typedef unsigned u32;
typedef unsigned long long u64;

// ---------------- packed f32x2 helpers ----------------
__device__ __forceinline__ u64 ffma2(u64 a, u64 b, u64 c) {
    u64 d; asm("fma.rn.f32x2 %0, %1, %2, %3;" : "=l"(d) : "l"(a), "l"(b), "l"(c)); return d;
}
__device__ __forceinline__ u64 pk2(float lo, float hi) {
    u64 d; asm("mov.b64 %0, {%1, %2};" : "=l"(d) : "f"(lo), "f"(hi)); return d;
}
__device__ __forceinline__ void upk2(u64 v, float& lo, float& hi) {
    asm("mov.b64 {%0, %1}, %2;" : "=f"(lo), "=f"(hi) : "l"(v));
}
__device__ __forceinline__ u32 cvt2(float hi, float lo) {
    u32 r; asm("cvt.rn.bf16x2.f32 %0, %1, %2;" : "=r"(r) : "f"(hi), "f"(lo)); return r;
}
__device__ __forceinline__ float bf16rt(float x) {
    return __bfloat162float(__float2bfloat16_rn(x));
}
__device__ __forceinline__ void mma16816(float c[4], const u32 a[4], u32 b0, u32 b1) {
    asm volatile(
        "mma.sync.aligned.m16n8k16.row.col.f32.bf16.bf16.f32 "
        "{%0,%1,%2,%3},{%4,%5,%6,%7},{%8,%9},{%0,%1,%2,%3};"
        : "+f"(c[0]), "+f"(c[1]), "+f"(c[2]), "+f"(c[3])
        : "r"(a[0]), "r"(a[1]), "r"(a[2]), "r"(a[3]), "r"(b0), "r"(b1));
}

// ---------------- scratch (device globals) ----------------
__device__ float g_topo[BB*NNODE];
__device__ u32   g_edge[NNODE*NWRD];
__device__ u32   g_colbits[BB*NWRD];
__device__ __nv_bfloat16 g_Qh[(size_t)BB*HH*NNODE*HDIM];
__device__ __nv_bfloat16 g_Ql[(size_t)BB*HH*NNODE*HDIM];
__device__ u32 g_Ki[(size_t)BB*HH*NNODE*32];
__device__ u32 g_Vi[(size_t)BB*HH*HDIM*2048];
__device__ float g_attn[(size_t)BB*NNODE*DDIM];

// =====================================================================
// LAUNCH 1: blocks [0,512) zero edge bits; blocks [512,768) topo MLP
// =====================================================================
__global__ void __launch_bounds__(256) k_pre1(
        const float* __restrict__ x,
        const float* __restrict__ g1w, const float* __restrict__ g1b,
        const float* __restrict__ g2w, const float* __restrict__ g2b) {
    int bx = blockIdx.x;
    int t = threadIdx.x;
    if (bx < 512) {
        g_edge[bx * 256 + t] = 0u;
        return;
    }
    // ---- topo: 16 nodes per block, 256 threads (2 halves x 128 hidden units) ----
    __shared__ __align__(16) float xs[16][DDIM];
    __shared__ float rs[16][4];
    int tl = t & 127;            // hidden unit
    int g = t >> 7;              // node half (0: nodes 0-7, 1: nodes 8-15)
    int base = (bx - 512) * 16;  // flattened node index

    const float4* xv = (const float4*)(x + (size_t)base * DDIM);
    float4* xsv = (float4*)&xs[0][0];
    #pragma unroll
    for (int r = 0; r < 4; r++) xsv[t + r * 256] = xv[t + r * 256];
    __syncthreads();

    u64 acc[8];
    #pragma unroll
    for (int nn = 0; nn < 8; nn++) acc[nn] = 0ull;

    const ulonglong2* wrow = (const ulonglong2*)(g1w + (size_t)tl * DDIM);
    #pragma unroll 4
    for (int k4 = 0; k4 < DDIM/4; k4++) {
        ulonglong2 wv = wrow[k4];
        #pragma unroll
        for (int nn = 0; nn < 8; nn++) {
            ulonglong2 xp = ((const ulonglong2*)xs[g * 8 + nn])[k4];
            acc[nn] = ffma2(wv.x, xp.x, acc[nn]);
            acc[nn] = ffma2(wv.y, xp.y, acc[nn]);
        }
    }
    float b1 = g1b[tl];
    float w2s = g2w[tl];
    float res[8];
    #pragma unroll
    for (int nn = 0; nn < 8; nn++) {
        float lo, hi; upk2(acc[nn], lo, hi);
        float h = fmaxf(lo + hi + b1, 0.0f);
        res[nn] = h * w2s;
    }
    int lane = t & 31, wrp = tl >> 5;
    #pragma unroll
    for (int nn = 0; nn < 8; nn++) {
        float v = res[nn];
        #pragma unroll
        for (int o = 16; o > 0; o >>= 1) v += __shfl_down_sync(0xffffffffu, v, o);
        if (lane == 0) rs[g * 8 + nn][wrp] = v;
    }
    __syncthreads();
    if (tl < 8) {
        int node = g * 8 + tl;
        float v = rs[node][0] + rs[node][1] + rs[node][2] + rs[node][3];
        g_topo[base + node] = v + g2b[0];
    }
}

// =====================================================================
// LAUNCH 2 bodies
// =====================================================================
// ---- QKV GEMM body (blocks 0..383) ----
__device__ void qkv_body(int bx,
        const float* __restrict__ A,
        const float* __restrict__ qw, const float* __restrict__ qb,
        const float* __restrict__ kw, const float* __restrict__ kb,
        const float* __restrict__ vw, const float* __restrict__ vb,
        u32* __restrict__ Qh, u32* __restrict__ Ql,
        u32* __restrict__ Ki, u32* __restrict__ Vi, float qscale) {
    __shared__ __align__(16) u64   As2[16][130];
    __shared__ __align__(16) float Ws[16][68];
    int mode = bx >> 7;
    int rem = bx & 127;
    int m0 = (rem & 31) * 128, c0 = (rem >> 5) * 64;
    const float* W    = (mode == 0) ? qw : (mode == 1) ? kw : vw;
    const float* bias = (mode == 0) ? qb : (mode == 1) ? kb : vb;
    float scale = (mode == 0) ? qscale : 1.0f;

    int tid = threadIdx.x;
    int tx = tid & 15;
    int rg = tid >> 4;
    int lkk = tid & 15, lm = tid >> 4;

    u64 acc[8][2];
    #pragma unroll
    for (int i = 0; i < 8; i++) { acc[i][0] = 0ull; acc[i][1] = 0ull; }

    for (int k0 = 0; k0 < DDIM; k0 += 16) {
        #pragma unroll
        for (int rr = 0; rr < 8; rr++) {
            int m = lm + 16 * rr;
            float v = A[(size_t)(m0 + m) * DDIM + k0 + lkk];
            As2[lkk][m] = pk2(v, v);
        }
        #pragma unroll
        for (int rr = 0; rr < 4; rr++) {
            int c = lm + 16 * rr;
            Ws[lkk][c] = W[(size_t)(c0 + c) * DDIM + k0 + lkk];
        }
        __syncthreads();
        #pragma unroll
        for (int kk = 0; kk < 16; kk++) {
            float4 w4 = *(const float4*)&Ws[kk][tx * 4];
            u64 w01 = pk2(w4.x, w4.y), w23 = pk2(w4.z, w4.w);
            const u64* arow = &As2[kk][rg * 8];
            #pragma unroll
            for (int ii = 0; ii < 8; ii += 2) {
                ulonglong2 a2 = *(const ulonglong2*)&arow[ii];
                acc[ii][0]     = ffma2(a2.x, w01, acc[ii][0]);
                acc[ii][1]     = ffma2(a2.x, w23, acc[ii][1]);
                acc[ii + 1][0] = ffma2(a2.y, w01, acc[ii + 1][0]);
                acc[ii + 1][1] = ffma2(a2.y, w23, acc[ii + 1][1]);
            }
        }
        __syncthreads();
    }

    float4 b4 = *(const float4*)&bias[c0 + tx * 4];
    int c = c0 + tx * 4;
    int h = (c >> 5) & 7, cw = c & 31;
    int bb = m0 >> 11;
    int n0 = (m0 & 2047) + rg * 8;
    int bh = bb * HH + h;

    if (mode == 2) {
        float vals[8][4];
        #pragma unroll
        for (int ii = 0; ii < 8; ii++) {
            float f0, f1, f2, f3;
            upk2(acc[ii][0], f0, f1);
            upk2(acc[ii][1], f2, f3);
            vals[ii][0] = f0 + b4.x; vals[ii][1] = f1 + b4.y;
            vals[ii][2] = f2 + b4.z; vals[ii][3] = f3 + b4.w;
        }
        int w0v = n0 >> 1;
        int jt = w0v >> 6;
        int s8 = (w0v & 63) >> 3;
        int slot = (w0v >> 2) & 1;
        #pragma unroll
        for (int jj = 0; jj < 4; jj++) {
            int d = cw + jj;
            size_t dbase = ((size_t)bh * HDIM + d) * 2048;
            #pragma unroll
            for (int p = 0; p < 4; p++) {
                float v0 = vals[2*p][jj], v1 = vals[2*p+1][jj];
                float h0 = bf16rt(v0), h1 = bf16rt(v1);
                size_t ub = dbase + (size_t)(jt * 32 + s8 * 4 + p) * 4;
                Vi[ub + slot]     = cvt2(h1, h0);
                Vi[ub + slot + 2] = cvt2(v1 - h1, v0 - h0);
            }
        }
    } else if (mode == 1) {
        int w0 = cw >> 1;
        int kc = w0 >> 3, t0 = w0 & 7;
        int u0 = kc * 4 + (t0 & 3);
        int s = t0 >> 2;
        #pragma unroll
        for (int ii = 0; ii < 8; ii++) {
            float f0, f1, f2, f3;
            upk2(acc[ii][0], f0, f1);
            upk2(acc[ii][1], f2, f3);
            f0 += b4.x; f1 += b4.y; f2 += b4.z; f3 += b4.w;
            float h0 = bf16rt(f0), h1 = bf16rt(f1), h2 = bf16rt(f2), h3 = bf16rt(f3);
            int n = n0 + ii;
            size_t rb = ((size_t)bh * NNODE + n) * 32;
            Ki[rb + u0*4 + s]           = cvt2(h1, h0);
            Ki[rb + (u0+1)*4 + s]       = cvt2(h3, h2);
            Ki[rb + u0*4 + s + 2]       = cvt2(f1 - h1, f0 - h0);
            Ki[rb + (u0+1)*4 + s + 2]   = cvt2(f3 - h3, f2 - h2);
        }
    } else {
        #pragma unroll
        for (int ii = 0; ii < 8; ii++) {
            float f0, f1, f2, f3;
            upk2(acc[ii][0], f0, f1);
            upk2(acc[ii][1], f2, f3);
            f0 = (f0 + b4.x) * scale; f1 = (f1 + b4.y) * scale;
            f2 = (f2 + b4.z) * scale; f3 = (f3 + b4.w) * scale;
            float h0 = bf16rt(f0), h1 = bf16rt(f1), h2 = bf16rt(f2), h3 = bf16rt(f3);
            int n = n0 + ii;
            size_t widx = ((size_t)bh * NNODE + n) * (HDIM/2) + (cw >> 1);
            *(uint2*)&Qh[widx] = make_uint2(cvt2(h1, h0), cvt2(h3, h2));
            *(uint2*)&Ql[widx] = make_uint2(cvt2(f1 - h1, f0 - h0), cvt2(f3 - h3, f2 - h2));
        }
    }
}

// ---- top-k body (blocks 640..641): exact radix select ----
__device__ void topk_body(int b) {
    __shared__ u32 keys[NNODE];
    __shared__ u32 hist[256];
    __shared__ u32 sb[256];
    __shared__ u32 scn[256];
    __shared__ u32 sh_prefix, sh_remain;
    int t = threadIdx.x;

    if (t < NWRD) g_colbits[b * NWRD + t] = 0u;

    for (int i = t; i < NNODE; i += 256) {
        u32 u = __float_as_uint(g_topo[b * NNODE + i]);
        u = (u & 0x80000000u) ? ~u : (u | 0x80000000u);
        keys[i] = u;
    }
    u32 prefix = 0, remain = KTOP;
    __syncthreads();

    for (int shift = 24; shift >= 0; shift -= 8) {
        hist[t] = 0;
        __syncthreads();
        for (int i = t; i < NNODE; i += 256) {
            u32 k = keys[i];
            bool in_group = (shift == 24) || ((k >> (shift + 8)) == prefix);
            if (in_group) atomicAdd(&hist[(k >> shift) & 255], 1u);
        }
        __syncthreads();
        sb[t] = hist[t];
        __syncthreads();
        for (int ofs = 1; ofs < 256; ofs <<= 1) {
            u32 add = (t + ofs < 256) ? sb[t + ofs] : 0u;
            __syncthreads();
            sb[t] += add;
            __syncthreads();
        }
        u32 above = (t == 255) ? 0u : sb[t + 1];
        if (sb[t] >= remain && above < remain) {
            sh_prefix = (prefix << 8) | (u32)t;
            sh_remain = remain - above;
        }
        __syncthreads();
        prefix = sh_prefix;
        remain = sh_remain;
        __syncthreads();
    }
    u32 T = prefix;

    u32 cnt = 0;
    #pragma unroll
    for (int u = 0; u < 8; u++) if (keys[t * 8 + u] == T) cnt++;
    scn[t] = cnt;
    __syncthreads();
    for (int ofs = 1; ofs < 256; ofs <<= 1) {
        u32 v = scn[t];
        u32 add = (t >= ofs) ? scn[t - ofs] : 0u;
        __syncthreads();
        scn[t] = v + add;
        __syncthreads();
    }
    u32 taken = scn[t] - cnt;
    u32 byte = 0;
    #pragma unroll
    for (int u = 0; u < 8; u++) {
        u32 k = keys[t * 8 + u];
        bool m = false;
        if (k > T) m = true;
        else if (k == T) { if (taken < remain) m = true; taken++; }
        if (m) byte |= (1u << u);
    }
    atomicOr(&g_colbits[b * NWRD + (t >> 2)], byte << ((t & 3) * 8));
}

// ---- fused launch 2: QKV gemm (384) | edge scatter (256) | topk (2) ----
__global__ void __launch_bounds__(256) k_pre2(
        const float* __restrict__ x, const int* __restrict__ ei,
        const float* __restrict__ qw, const float* __restrict__ qb,
        const float* __restrict__ kw, const float* __restrict__ kb,
        const float* __restrict__ vw, const float* __restrict__ vb,
        u32* __restrict__ Qh, u32* __restrict__ Ql,
        u32* __restrict__ Ki, u32* __restrict__ Vi, float qscale) {
    int bx = blockIdx.x;
    if (bx < 384) {
        qkv_body(bx, x, qw, qb, kw, kb, vw, vb, Qh, Ql, Ki, Vi, qscale);
    } else if (bx < 640) {
        int e = (bx - 384) * 256 + threadIdx.x;
        int r = ei[e];
        int c = ei[EEDGE + e];
        atomicOr(&g_edge[r * NWRD + (c >> 5)], 1u << (c & 31));
    } else {
        topk_body(bx - 640);
    }
}

// =====================================================================
// LAUNCH 3: fused masked attention + mask writeback (inline edge|col merge)
// =====================================================================
__global__ void __launch_bounds__(128) k_attn(float* __restrict__ outMask) {
    __shared__ __align__(16) uint4 Ks4[128 * 12];
    __shared__ __align__(16) uint4 Vs4[32 * 36];
    __shared__ __align__(16) u32 eW[128][4];

    int tid = threadIdx.x;
    int wp = tid >> 5, lane = tid & 31;
    int gid = lane >> 2, tig = lane & 3;
    int bh = blockIdx.y, b = bh >> 3, h = bh & 7;
    int i0 = blockIdx.x * 128;

    const u32* gqh = (const u32*)g_Qh;
    const u32* gql = (const u32*)g_Ql;
    const uint4* gKi = (const uint4*)g_Ki;
    const uint4* gVi = (const uint4*)g_Vi;
    const uint4* gE  = (const uint4*)g_edge;

    u32 qh[2][2][4], ql[2][2][4];
    #pragma unroll
    for (int s = 0; s < 2; s++) {
        size_t blo = ((size_t)bh * NNODE + i0 + s * 64 + wp * 16 + gid) * 16;
        size_t bhi = blo + 8 * 16;
        #pragma unroll
        for (int kc = 0; kc < 2; kc++) {
            qh[s][kc][0] = gqh[blo + kc*8 + tig];
            qh[s][kc][1] = gqh[bhi + kc*8 + tig];
            qh[s][kc][2] = gqh[blo + kc*8 + tig + 4];
            qh[s][kc][3] = gqh[bhi + kc*8 + tig + 4];
            ql[s][kc][0] = gql[blo + kc*8 + tig];
            ql[s][kc][1] = gql[bhi + kc*8 + tig];
            ql[s][kc][2] = gql[blo + kc*8 + tig + 4];
            ql[s][kc][3] = gql[bhi + kc*8 + tig + 4];
        }
    }

    float oc[2][4][4];
    #pragma unroll
    for (int s = 0; s < 2; s++)
        #pragma unroll
        for (int vt = 0; vt < 4; vt++)
            #pragma unroll
            for (int e = 0; e < 4; e++) oc[s][vt][e] = 0.0f;
    float sl[2] = {0.0f, 0.0f}, sh[2] = {0.0f, 0.0f};

    for (int j0 = 0; j0 < NNODE; j0 += 128) {
        __syncthreads();
        for (int idx = tid; idx < 1024; idx += 128) {
            int r = idx >> 3, g = idx & 7;
            Ks4[r * 12 + g] = gKi[((size_t)bh * NNODE + j0 + r) * 8 + g];
        }
        for (int idx = tid; idx < 1024; idx += 128) {
            int d = idx >> 5, gv = idx & 31;
            Vs4[d * 36 + gv] = gVi[((size_t)bh * HDIM + d) * 512 + (j0 >> 7) * 32 + gv];
        }
        // stage mask bits: edge | colbits (inline merge)
        {
            uint4 cb = *(const uint4*)&g_colbits[b * NWRD + (j0 >> 5)];
            uint4 e4 = gE[(size_t)(i0 + tid) * 16 + (j0 >> 7)];
            eW[tid][0] = e4.x | cb.x; eW[tid][1] = e4.y | cb.y;
            eW[tid][2] = e4.z | cb.z; eW[tid][3] = e4.w | cb.w;
        }
        __syncthreads();

        // coalesced sparse_mask writeback (streaming)
        {
            #pragma unroll 8
            for (int rr = 0; rr < 32; rr++) {
                int r = wp + rr * 4;
                u32 bits = eW[r][lane >> 3];
                int bo = (lane & 7) * 4;
                float4 f;
                f.x = (bits >> (bo + 0)) & 1u ? 1.0f : 0.0f;
                f.y = (bits >> (bo + 1)) & 1u ? 1.0f : 0.0f;
                f.z = (bits >> (bo + 2)) & 1u ? 1.0f : 0.0f;
                f.w = (bits >> (bo + 3)) & 1u ? 1.0f : 0.0f;
                __stcs((float4*)(outMask + ((size_t)bh * NNODE + i0 + r) * NNODE + j0) + lane, f);
            }
        }

        #pragma unroll 1
        for (int sub = 0; sub < 4; sub++) {
            float sc[2][4][4];
            #pragma unroll
            for (int s = 0; s < 2; s++)
                #pragma unroll
                for (int nt = 0; nt < 4; nt++)
                    #pragma unroll
                    for (int e = 0; e < 4; e++) sc[s][nt][e] = 0.0f;
            #pragma unroll
            for (int kc = 0; kc < 2; kc++)
                #pragma unroll
                for (int nt = 0; nt < 4; nt++) {
                    int jr = sub * 32 + nt * 8 + gid;
                    uint4 kf = Ks4[jr * 12 + kc * 4 + tig];
                    mma16816(sc[0][nt], qh[0][kc], kf.x, kf.y);
                    mma16816(sc[0][nt], ql[0][kc], kf.x, kf.y);
                    mma16816(sc[0][nt], qh[0][kc], kf.z, kf.w);
                    mma16816(sc[1][nt], qh[1][kc], kf.x, kf.y);
                    mma16816(sc[1][nt], ql[1][kc], kf.x, kf.y);
                    mma16816(sc[1][nt], qh[1][kc], kf.z, kf.w);
                }
            u32 ph[2][2][4], pl[2][2][4];
            #pragma unroll
            for (int s = 0; s < 2; s++) {
                u32 wlo = eW[s * 64 + wp * 16 + gid][sub];
                u32 whi = eW[s * 64 + wp * 16 + gid + 8][sub];
                float pm[4][4];
                #pragma unroll
                for (int nt = 0; nt < 4; nt++) {
                    float p0 = __expf(sc[s][nt][0]);
                    float p1 = __expf(sc[s][nt][1]);
                    float p2 = __expf(sc[s][nt][2]);
                    float p3 = __expf(sc[s][nt][3]);
                    int bp = nt * 8 + tig * 2;
                    float m0 = ((wlo >> bp) & 1u) ? p0 : 0.0f;
                    float m1 = ((wlo >> (bp + 1)) & 1u) ? p1 : 0.0f;
                    float m2 = ((whi >> bp) & 1u) ? p2 : 0.0f;
                    float m3 = ((whi >> (bp + 1)) & 1u) ? p3 : 0.0f;
                    sl[s] += m0 + m1; sh[s] += m2 + m3;
                    pm[nt][0] = m0; pm[nt][1] = m1; pm[nt][2] = m2; pm[nt][3] = m3;
                }
                #pragma unroll
                for (int kc = 0; kc < 2; kc++) {
                    int na = kc * 2, nb = kc * 2 + 1;
                    float h00 = bf16rt(pm[na][0]), h01 = bf16rt(pm[na][1]);
                    float h02 = bf16rt(pm[na][2]), h03 = bf16rt(pm[na][3]);
                    float h10 = bf16rt(pm[nb][0]), h11 = bf16rt(pm[nb][1]);
                    float h12 = bf16rt(pm[nb][2]), h13 = bf16rt(pm[nb][3]);
                    ph[s][kc][0] = cvt2(h01, h00);
                    ph[s][kc][1] = cvt2(h03, h02);
                    ph[s][kc][2] = cvt2(h11, h10);
                    ph[s][kc][3] = cvt2(h13, h12);
                    pl[s][kc][0] = cvt2(pm[na][1] - h01, pm[na][0] - h00);
                    pl[s][kc][1] = cvt2(pm[na][3] - h03, pm[na][2] - h02);
                    pl[s][kc][2] = cvt2(pm[nb][1] - h11, pm[nb][0] - h10);
                    pl[s][kc][3] = cvt2(pm[nb][3] - h13, pm[nb][2] - h12);
                }
            }
            #pragma unroll
            for (int kc = 0; kc < 2; kc++)
                #pragma unroll
                for (int vt = 0; vt < 4; vt++) {
                    int d = vt * 8 + gid;
                    uint4 vf = Vs4[d * 36 + (sub * 2 + kc) * 4 + tig];
                    mma16816(oc[0][vt], ph[0][kc], vf.x, vf.y);
                    mma16816(oc[0][vt], pl[0][kc], vf.x, vf.y);
                    mma16816(oc[0][vt], ph[0][kc], vf.z, vf.w);
                    mma16816(oc[1][vt], ph[1][kc], vf.x, vf.y);
                    mma16816(oc[1][vt], pl[1][kc], vf.x, vf.y);
                    mma16816(oc[1][vt], ph[1][kc], vf.z, vf.w);
                }
        }
    }

    #pragma unroll
    for (int s = 0; s < 2; s++) {
        float slo = sl[s], shi = sh[s];
        #pragma unroll
        for (int o = 1; o <= 2; o <<= 1) {
            slo += __shfl_xor_sync(0xffffffffu, slo, o);
            shi += __shfl_xor_sync(0xffffffffu, shi, o);
        }
        float invlo = 1.0f / slo;
        float invhi = 1.0f / shi;
        int nlo = i0 + s * 64 + wp * 16 + gid;
        int nhi = nlo + 8;
        size_t olo = ((size_t)(b * NNODE + nlo)) * DDIM + h * HDIM;
        size_t ohi = ((size_t)(b * NNODE + nhi)) * DDIM + h * HDIM;
        #pragma unroll
        for (int vt = 0; vt < 4; vt++) {
            int d = vt * 8 + tig * 2;
            *(float2*)&g_attn[olo + d] = make_float2(oc[s][vt][0] * invlo, oc[s][vt][1] * invlo);
            *(float2*)&g_attn[ohi + d] = make_float2(oc[s][vt][2] * invhi, oc[s][vt][3] * invhi);
        }
    }
}

// =====================================================================
// LAUNCH 4: O projection GEMM (fp32 out)
// =====================================================================
__global__ void __launch_bounds__(256) k_gemmO(const float* __restrict__ A, const float* __restrict__ W,
                       const float* __restrict__ bias, float* __restrict__ OutF) {
    __shared__ __align__(16) u64   As2[16][130];
    __shared__ __align__(16) float Ws[16][68];
    int tid = threadIdx.x;
    int tx = tid & 15;
    int rg = tid >> 4;
    int m0 = blockIdx.x * 128, c0 = blockIdx.y * 64;
    int lkk = tid & 15, lm = tid >> 4;

    u64 acc[8][2];
    #pragma unroll
    for (int i = 0; i < 8; i++) { acc[i][0] = 0ull; acc[i][1] = 0ull; }

    for (int k0 = 0; k0 < DDIM; k0 += 16) {
        #pragma unroll
        for (int rr = 0; rr < 8; rr++) {
            int m = lm + 16 * rr;
            float v = A[(size_t)(m0 + m) * DDIM + k0 + lkk];
            As2[lkk][m] = pk2(v, v);
        }
        #pragma unroll
        for (int rr = 0; rr < 4; rr++) {
            int c = lm + 16 * rr;
            Ws[lkk][c] = W[(size_t)(c0 + c) * DDIM + k0 + lkk];
        }
        __syncthreads();
        #pragma unroll
        for (int kk = 0; kk < 16; kk++) {
            float4 w4 = *(const float4*)&Ws[kk][tx * 4];
            u64 w01 = pk2(w4.x, w4.y), w23 = pk2(w4.z, w4.w);
            const u64* arow = &As2[kk][rg * 8];
            #pragma unroll
            for (int ii = 0; ii < 8; ii += 2) {
                ulonglong2 a2 = *(const ulonglong2*)&arow[ii];
                acc[ii][0]     = ffma2(a2.x, w01, acc[ii][0]);
                acc[ii][1]     = ffma2(a2.x, w23, acc[ii][1]);
                acc[ii + 1][0] = ffma2(a2.y, w01, acc[ii + 1][0]);
                acc[ii + 1][1] = ffma2(a2.y, w23, acc[ii + 1][1]);
            }
        }
        __syncthreads();
    }

    float4 b4 = *(const float4*)&bias[c0 + tx * 4];
    int c = c0 + tx * 4;
    #pragma unroll
    for (int ii = 0; ii < 8; ii++) {
        int m = m0 + rg * 8 + ii;
        float f0, f1, f2, f3;
        upk2(acc[ii][0], f0, f1);
        upk2(acc[ii][1], f2, f3);
        *(float4*)&OutF[(size_t)m * DDIM + c] =
            make_float4(f0 + b4.x, f1 + b4.y, f2 + b4.z, f3 + b4.w);
    }
}

// ---------------- launch (4 launches, single stream, graph-capturable) ----------------
extern "C" void kernel_launch(void* const* d_in, const int* in_sizes, int n_in,
                              void* d_out, int out_size) {
    (void)in_sizes; (void)n_in; (void)out_size;
    const float* x   = (const float*)d_in[0];
    const int*   ei  = (const int*)  d_in[1];
    const float* qw  = (const float*)d_in[2];
    const float* qb  = (const float*)d_in[3];
    const float* kw  = (const float*)d_in[4];
    const float* kb  = (const float*)d_in[5];
    const float* vw  = (const float*)d_in[6];
    const float* vb  = (const float*)d_in[7];
    const float* ow  = (const float*)d_in[8];
    const float* ob  = (const float*)d_in[9];
    const float* g1w = (const float*)d_in[10];
    const float* g1b = (const float*)d_in[11];
    const float* g2w = (const float*)d_in[12];
    const float* g2b = (const float*)d_in[13];

    float* out = (float*)d_out;
    float* outMask = out + (size_t)BB * NNODE * DDIM;

    u32 *pQh, *pQl, *pKi, *pVi;
    float* pAttn;
    cudaGetSymbolAddress((void**)&pQh, g_Qh);
    cudaGetSymbolAddress((void**)&pQl, g_Ql);
    cudaGetSymbolAddress((void**)&pKi, g_Ki);
    cudaGetSymbolAddress((void**)&pVi, g_Vi);
    cudaGetSymbolAddress((void**)&pAttn, g_attn);

    const float qscale = 0.17677669529663687f;  // 1/sqrt(32)

    k_pre1<<<768, 256>>>(x, g1w, g1b, g2w, g2b);
    k_pre2<<<642, 256>>>(x, ei, qw, qb, kw, kb, vw, vb,
                         pQh, pQl, pKi, pVi, qscale);
    k_attn<<<dim3(NNODE / 128, BB * HH), 128>>>(outMask);
    k_gemmO<<<dim3(BB * NNODE / 128, DDIM / 64), 256>>>(pAttn, ow, ob, out);
}

// round 11
// speedup vs baseline: 1.0026x; 1.0026x over previous
#include <cuda_runtime.h>
#include <cuda_bf16.h>
#include <cstdint>
#include <cstddef>

#define BB 2
#define NNODE 2048
#define DDIM 256
#define HH 8
#define HDIM 32
#define EEDGE 65536
#define KTOP 1024
#define NWRD (NNODE/32)   // 64 u32 words per adjacency row

typedef unsigned u32;
typedef unsigned long long u64;

// ---------------- packed f32x2 helpers ----------------
__device__ __forceinline__ u64 ffma2(u64 a, u64 b, u64 c) {
    u64 d; asm("fma.rn.f32x2 %0, %1, %2, %3;" : "=l"(d) : "l"(a), "l"(b), "l"(c)); return d;
}
__device__ __forceinline__ u64 pk2(float lo, float hi) {
    u64 d; asm("mov.b64 %0, {%1, %2};" : "=l"(d) : "f"(lo), "f"(hi)); return d;
}
__device__ __forceinline__ void upk2(u64 v, float& lo, float& hi) {
    asm("mov.b64 {%0, %1}, %2;" : "=f"(lo), "=f"(hi) : "l"(v));
}
__device__ __forceinline__ u32 cvt2(float hi, float lo) {
    u32 r; asm("cvt.rn.bf16x2.f32 %0, %1, %2;" : "=r"(r) : "f"(hi), "f"(lo)); return r;
}
__device__ __forceinline__ float bf16rt(float x) {
    return __bfloat162float(__float2bfloat16_rn(x));
}
__device__ __forceinline__ void mma16816(float c[4], const u32 a[4], u32 b0, u32 b1) {
    asm volatile(
        "mma.sync.aligned.m16n8k16.row.col.f32.bf16.bf16.f32 "
        "{%0,%1,%2,%3},{%4,%5,%6,%7},{%8,%9},{%0,%1,%2,%3};"
        : "+f"(c[0]), "+f"(c[1]), "+f"(c[2]), "+f"(c[3])
        : "r"(a[0]), "r"(a[1]), "r"(a[2]), "r"(a[3]), "r"(b0), "r"(b1));
}

// ---------------- scratch (device globals) ----------------
__device__ float g_topo[BB*NNODE];
__device__ u32   g_edge[NNODE*NWRD];
__device__ u32   g_colbits[BB*NWRD];
__device__ __nv_bfloat16 g_Qh[(size_t)BB*HH*NNODE*HDIM];
__device__ __nv_bfloat16 g_Ql[(size_t)BB*HH*NNODE*HDIM];
__device__ u32 g_Ki[(size_t)BB*HH*NNODE*32];
__device__ u32 g_Vi[(size_t)BB*HH*HDIM*2048];
__device__ float g_attn[(size_t)BB*NNODE*DDIM];

// =====================================================================
// LAUNCH 1: blocks [0,512) zero edge bits; blocks [512,768) topo MLP
// =====================================================================
__global__ void __launch_bounds__(256) k_pre1(
        const float* __restrict__ x,
        const float* __restrict__ g1w, const float* __restrict__ g1b,
        const float* __restrict__ g2w, const float* __restrict__ g2b) {
    int bx = blockIdx.x;
    int t = threadIdx.x;
    if (bx < 512) {
        g_edge[bx * 256 + t] = 0u;
        return;
    }
    // ---- topo: 16 nodes per block, 256 threads (2 halves x 128 hidden units) ----
    __shared__ __align__(16) float xs[16][DDIM];
    __shared__ float rs[16][4];
    int tl = t & 127;            // hidden unit
    int g = t >> 7;              // node half (0: nodes 0-7, 1: nodes 8-15)
    int base = (bx - 512) * 16;  // flattened node index

    const float4* xv = (const float4*)(x + (size_t)base * DDIM);
    float4* xsv = (float4*)&xs[0][0];
    #pragma unroll
    for (int r = 0; r < 4; r++) xsv[t + r * 256] = xv[t + r * 256];
    __syncthreads();

    u64 acc[8];
    #pragma unroll
    for (int nn = 0; nn < 8; nn++) acc[nn] = 0ull;

    const ulonglong2* wrow = (const ulonglong2*)(g1w + (size_t)tl * DDIM);
    #pragma unroll 4
    for (int k4 = 0; k4 < DDIM/4; k4++) {
        ulonglong2 wv = wrow[k4];
        #pragma unroll
        for (int nn = 0; nn < 8; nn++) {
            ulonglong2 xp = ((const ulonglong2*)xs[g * 8 + nn])[k4];
            acc[nn] = ffma2(wv.x, xp.x, acc[nn]);
            acc[nn] = ffma2(wv.y, xp.y, acc[nn]);
        }
    }
    float b1 = g1b[tl];
    float w2s = g2w[tl];
    float res[8];
    #pragma unroll
    for (int nn = 0; nn < 8; nn++) {
        float lo, hi; upk2(acc[nn], lo, hi);
        float h = fmaxf(lo + hi + b1, 0.0f);
        res[nn] = h * w2s;
    }
    int lane = t & 31, wrp = tl >> 5;
    #pragma unroll
    for (int nn = 0; nn < 8; nn++) {
        float v = res[nn];
        #pragma unroll
        for (int o = 16; o > 0; o >>= 1) v += __shfl_down_sync(0xffffffffu, v, o);
        if (lane == 0) rs[g * 8 + nn][wrp] = v;
    }
    __syncthreads();
    if (tl < 8) {
        int node = g * 8 + tl;
        float v = rs[node][0] + rs[node][1] + rs[node][2] + rs[node][3];
        g_topo[base + node] = v + g2b[0];
    }
}

// =====================================================================
// LAUNCH 2 bodies
// =====================================================================
// ---- QKV GEMM body (blocks 0..383) ----
__device__ void qkv_body(int bx,
        const float* __restrict__ A,
        const float* __restrict__ qw, const float* __restrict__ qb,
        const float* __restrict__ kw, const float* __restrict__ kb,
        const float* __restrict__ vw, const float* __restrict__ vb,
        u32* __restrict__ Qh, u32* __restrict__ Ql,
        u32* __restrict__ Ki, u32* __restrict__ Vi, float qscale) {
    __shared__ __align__(16) u64   As2[16][130];
    __shared__ __align__(16) float Ws[16][68];
    int mode = bx >> 7;
    int rem = bx & 127;
    int m0 = (rem & 31) * 128, c0 = (rem >> 5) * 64;
    const float* W    = (mode == 0) ? qw : (mode == 1) ? kw : vw;
    const float* bias = (mode == 0) ? qb : (mode == 1) ? kb : vb;
    float scale = (mode == 0) ? qscale : 1.0f;

    int tid = threadIdx.x;
    int tx = tid & 15;
    int rg = tid >> 4;
    int lkk = tid & 15, lm = tid >> 4;

    u64 acc[8][2];
    #pragma unroll
    for (int i = 0; i < 8; i++) { acc[i][0] = 0ull; acc[i][1] = 0ull; }

    for (int k0 = 0; k0 < DDIM; k0 += 16) {
        #pragma unroll
        for (int rr = 0; rr < 8; rr++) {
            int m = lm + 16 * rr;
            float v = A[(size_t)(m0 + m) * DDIM + k0 + lkk];
            As2[lkk][m] = pk2(v, v);
        }
        #pragma unroll
        for (int rr = 0; rr < 4; rr++) {
            int c = lm + 16 * rr;
            Ws[lkk][c] = W[(size_t)(c0 + c) * DDIM + k0 + lkk];
        }
        __syncthreads();
        #pragma unroll
        for (int kk = 0; kk < 16; kk++) {
            float4 w4 = *(const float4*)&Ws[kk][tx * 4];
            u64 w01 = pk2(w4.x, w4.y), w23 = pk2(w4.z, w4.w);
            const u64* arow = &As2[kk][rg * 8];
            #pragma unroll
            for (int ii = 0; ii < 8; ii += 2) {
                ulonglong2 a2 = *(const ulonglong2*)&arow[ii];
                acc[ii][0]     = ffma2(a2.x, w01, acc[ii][0]);
                acc[ii][1]     = ffma2(a2.x, w23, acc[ii][1]);
                acc[ii + 1][0] = ffma2(a2.y, w01, acc[ii + 1][0]);
                acc[ii + 1][1] = ffma2(a2.y, w23, acc[ii + 1][1]);
            }
        }
        __syncthreads();
    }

    float4 b4 = *(const float4*)&bias[c0 + tx * 4];
    int c = c0 + tx * 4;
    int h = (c >> 5) & 7, cw = c & 31;
    int bb = m0 >> 11;
    int n0 = (m0 & 2047) + rg * 8;
    int bh = bb * HH + h;

    if (mode == 2) {
        float vals[8][4];
        #pragma unroll
        for (int ii = 0; ii < 8; ii++) {
            float f0, f1, f2, f3;
            upk2(acc[ii][0], f0, f1);
            upk2(acc[ii][1], f2, f3);
            vals[ii][0] = f0 + b4.x; vals[ii][1] = f1 + b4.y;
            vals[ii][2] = f2 + b4.z; vals[ii][3] = f3 + b4.w;
        }
        int w0v = n0 >> 1;
        int jt = w0v >> 6;
        int s8 = (w0v & 63) >> 3;
        int slot = (w0v >> 2) & 1;
        #pragma unroll
        for (int jj = 0; jj < 4; jj++) {
            int d = cw + jj;
            size_t dbase = ((size_t)bh * HDIM + d) * 2048;
            #pragma unroll
            for (int p = 0; p < 4; p++) {
                float v0 = vals[2*p][jj], v1 = vals[2*p+1][jj];
                float h0 = bf16rt(v0), h1 = bf16rt(v1);
                size_t ub = dbase + (size_t)(jt * 32 + s8 * 4 + p) * 4;
                Vi[ub + slot]     = cvt2(h1, h0);
                Vi[ub + slot + 2] = cvt2(v1 - h1, v0 - h0);
            }
        }
    } else if (mode == 1) {
        int w0 = cw >> 1;
        int kc = w0 >> 3, t0 = w0 & 7;
        int u0 = kc * 4 + (t0 & 3);
        int s = t0 >> 2;
        #pragma unroll
        for (int ii = 0; ii < 8; ii++) {
            float f0, f1, f2, f3;
            upk2(acc[ii][0], f0, f1);
            upk2(acc[ii][1], f2, f3);
            f0 += b4.x; f1 += b4.y; f2 += b4.z; f3 += b4.w;
            float h0 = bf16rt(f0), h1 = bf16rt(f1), h2 = bf16rt(f2), h3 = bf16rt(f3);
            int n = n0 + ii;
            size_t rb = ((size_t)bh * NNODE + n) * 32;
            Ki[rb + u0*4 + s]           = cvt2(h1, h0);
            Ki[rb + (u0+1)*4 + s]       = cvt2(h3, h2);
            Ki[rb + u0*4 + s + 2]       = cvt2(f1 - h1, f0 - h0);
            Ki[rb + (u0+1)*4 + s + 2]   = cvt2(f3 - h3, f2 - h2);
        }
    } else {
        #pragma unroll
        for (int ii = 0; ii < 8; ii++) {
            float f0, f1, f2, f3;
            upk2(acc[ii][0], f0, f1);
            upk2(acc[ii][1], f2, f3);
            f0 = (f0 + b4.x) * scale; f1 = (f1 + b4.y) * scale;
            f2 = (f2 + b4.z) * scale; f3 = (f3 + b4.w) * scale;
            float h0 = bf16rt(f0), h1 = bf16rt(f1), h2 = bf16rt(f2), h3 = bf16rt(f3);
            int n = n0 + ii;
            size_t widx = ((size_t)bh * NNODE + n) * (HDIM/2) + (cw >> 1);
            *(uint2*)&Qh[widx] = make_uint2(cvt2(h1, h0), cvt2(h3, h2));
            *(uint2*)&Ql[widx] = make_uint2(cvt2(f1 - h1, f0 - h0), cvt2(f3 - h3, f2 - h2));
        }
    }
}

// ---- top-k body (blocks 640..641): exact radix select ----
__device__ void topk_body(int b) {
    __shared__ u32 keys[NNODE];
    __shared__ u32 hist[256];
    __shared__ u32 sb[256];
    __shared__ u32 scn[256];
    __shared__ u32 sh_prefix, sh_remain;
    int t = threadIdx.x;

    if (t < NWRD) g_colbits[b * NWRD + t] = 0u;

    for (int i = t; i < NNODE; i += 256) {
        u32 u = __float_as_uint(g_topo[b * NNODE + i]);
        u = (u & 0x80000000u) ? ~u : (u | 0x80000000u);
        keys[i] = u;
    }
    u32 prefix = 0, remain = KTOP;
    __syncthreads();

    for (int shift = 24; shift >= 0; shift -= 8) {
        hist[t] = 0;
        __syncthreads();
        for (int i = t; i < NNODE; i += 256) {
            u32 k = keys[i];
            bool in_group = (shift == 24) || ((k >> (shift + 8)) == prefix);
            if (in_group) atomicAdd(&hist[(k >> shift) & 255], 1u);
        }
        __syncthreads();
        sb[t] = hist[t];
        __syncthreads();
        for (int ofs = 1; ofs < 256; ofs <<= 1) {
            u32 add = (t + ofs < 256) ? sb[t + ofs] : 0u;
            __syncthreads();
            sb[t] += add;
            __syncthreads();
        }
        u32 above = (t == 255) ? 0u : sb[t + 1];
        if (sb[t] >= remain && above < remain) {
            sh_prefix = (prefix << 8) | (u32)t;
            sh_remain = remain - above;
        }
        __syncthreads();
        prefix = sh_prefix;
        remain = sh_remain;
        __syncthreads();
    }
    u32 T = prefix;

    u32 cnt = 0;
    #pragma unroll
    for (int u = 0; u < 8; u++) if (keys[t * 8 + u] == T) cnt++;
    scn[t] = cnt;
    __syncthreads();
    for (int ofs = 1; ofs < 256; ofs <<= 1) {
        u32 v = scn[t];
        u32 add = (t >= ofs) ? scn[t - ofs] : 0u;
        __syncthreads();
        scn[t] = v + add;
        __syncthreads();
    }
    u32 taken = scn[t] - cnt;
    u32 byte = 0;
    #pragma unroll
    for (int u = 0; u < 8; u++) {
        u32 k = keys[t * 8 + u];
        bool m = false;
        if (k > T) m = true;
        else if (k == T) { if (taken < remain) m = true; taken++; }
        if (m) byte |= (1u << u);
    }
    atomicOr(&g_colbits[b * NWRD + (t >> 2)], byte << ((t & 3) * 8));
}

// ---- fused launch 2: QKV gemm (384) | edge scatter (256) | topk (2) ----
__global__ void __launch_bounds__(256) k_pre2(
        const float* __restrict__ x, const int* __restrict__ ei,
        const float* __restrict__ qw, const float* __restrict__ qb,
        const float* __restrict__ kw, const float* __restrict__ kb,
        const float* __restrict__ vw, const float* __restrict__ vb,
        u32* __restrict__ Qh, u32* __restrict__ Ql,
        u32* __restrict__ Ki, u32* __restrict__ Vi, float qscale) {
    int bx = blockIdx.x;
    if (bx < 384) {
        qkv_body(bx, x, qw, qb, kw, kb, vw, vb, Qh, Ql, Ki, Vi, qscale);
    } else if (bx < 640) {
        int e = (bx - 384) * 256 + threadIdx.x;
        int r = ei[e];
        int c = ei[EEDGE + e];
        atomicOr(&g_edge[r * NWRD + (c >> 5)], 1u << (c & 31));
    } else {
        topk_body(bx - 640);
    }
}

// =====================================================================
// LAUNCH 3: fused masked attention + mask writeback (inline edge|col merge)
// =====================================================================
__global__ void __launch_bounds__(128) k_attn(float* __restrict__ outMask) {
    __shared__ __align__(16) uint4 Ks4[128 * 12];
    __shared__ __align__(16) uint4 Vs4[32 * 36];
    __shared__ __align__(16) u32 eW[128][4];

    int tid = threadIdx.x;
    int wp = tid >> 5, lane = tid & 31;
    int gid = lane >> 2, tig = lane & 3;
    int bh = blockIdx.y, b = bh >> 3, h = bh & 7;
    int i0 = blockIdx.x * 128;

    const u32* gqh = (const u32*)g_Qh;
    const u32* gql = (const u32*)g_Ql;
    const uint4* gKi = (const uint4*)g_Ki;
    const uint4* gVi = (const uint4*)g_Vi;
    const uint4* gE  = (const uint4*)g_edge;

    u32 qh[2][2][4], ql[2][2][4];
    #pragma unroll
    for (int s = 0; s < 2; s++) {
        size_t blo = ((size_t)bh * NNODE + i0 + s * 64 + wp * 16 + gid) * 16;
        size_t bhi = blo + 8 * 16;
        #pragma unroll
        for (int kc = 0; kc < 2; kc++) {
            qh[s][kc][0] = gqh[blo + kc*8 + tig];
            qh[s][kc][1] = gqh[bhi + kc*8 + tig];
            qh[s][kc][2] = gqh[blo + kc*8 + tig + 4];
            qh[s][kc][3] = gqh[bhi + kc*8 + tig + 4];
            ql[s][kc][0] = gql[blo + kc*8 + tig];
            ql[s][kc][1] = gql[bhi + kc*8 + tig];
            ql[s][kc][2] = gql[blo + kc*8 + tig + 4];
            ql[s][kc][3] = gql[bhi + kc*8 + tig + 4];
        }
    }

    float oc[2][4][4];
    #pragma unroll
    for (int s = 0; s < 2; s++)
        #pragma unroll
        for (int vt = 0; vt < 4; vt++)
            #pragma unroll
            for (int e = 0; e < 4; e++) oc[s][vt][e] = 0.0f;
    float sl[2] = {0.0f, 0.0f}, sh[2] = {0.0f, 0.0f};

    for (int j0 = 0; j0 < NNODE; j0 += 128) {
        __syncthreads();
        for (int idx = tid; idx < 1024; idx += 128) {
            int r = idx >> 3, g = idx & 7;
            Ks4[r * 12 + g] = gKi[((size_t)bh * NNODE + j0 + r) * 8 + g];
        }
        for (int idx = tid; idx < 1024; idx += 128) {
            int d = idx >> 5, gv = idx & 31;
            Vs4[d * 36 + gv] = gVi[((size_t)bh * HDIM + d) * 512 + (j0 >> 7) * 32 + gv];
        }
        // stage mask bits: edge | colbits (inline merge)
        {
            uint4 cb = *(const uint4*)&g_colbits[b * NWRD + (j0 >> 5)];
            uint4 e4 = gE[(size_t)(i0 + tid) * 16 + (j0 >> 7)];
            eW[tid][0] = e4.x | cb.x; eW[tid][1] = e4.y | cb.y;
            eW[tid][2] = e4.z | cb.z; eW[tid][3] = e4.w | cb.w;
        }
        __syncthreads();

        // coalesced sparse_mask writeback (streaming)
        {
            #pragma unroll 8
            for (int rr = 0; rr < 32; rr++) {
                int r = wp + rr * 4;
                u32 bits = eW[r][lane >> 3];
                int bo = (lane & 7) * 4;
                float4 f;
                f.x = (bits >> (bo + 0)) & 1u ? 1.0f : 0.0f;
                f.y = (bits >> (bo + 1)) & 1u ? 1.0f : 0.0f;
                f.z = (bits >> (bo + 2)) & 1u ? 1.0f : 0.0f;
                f.w = (bits >> (bo + 3)) & 1u ? 1.0f : 0.0f;
                __stcs((float4*)(outMask + ((size_t)bh * NNODE + i0 + r) * NNODE + j0) + lane, f);
            }
        }

        #pragma unroll 1
        for (int sub = 0; sub < 4; sub++) {
            float sc[2][4][4];
            #pragma unroll
            for (int s = 0; s < 2; s++)
                #pragma unroll
                for (int nt = 0; nt < 4; nt++)
                    #pragma unroll
                    for (int e = 0; e < 4; e++) sc[s][nt][e] = 0.0f;
            #pragma unroll
            for (int kc = 0; kc < 2; kc++)
                #pragma unroll
                for (int nt = 0; nt < 4; nt++) {
                    int jr = sub * 32 + nt * 8 + gid;
                    uint4 kf = Ks4[jr * 12 + kc * 4 + tig];
                    mma16816(sc[0][nt], qh[0][kc], kf.x, kf.y);
                    mma16816(sc[0][nt], ql[0][kc], kf.x, kf.y);
                    mma16816(sc[0][nt], qh[0][kc], kf.z, kf.w);
                    mma16816(sc[1][nt], qh[1][kc], kf.x, kf.y);
                    mma16816(sc[1][nt], ql[1][kc], kf.x, kf.y);
                    mma16816(sc[1][nt], qh[1][kc], kf.z, kf.w);
                }
            u32 ph[2][2][4], pl[2][2][4];
            #pragma unroll
            for (int s = 0; s < 2; s++) {
                u32 wlo = eW[s * 64 + wp * 16 + gid][sub];
                u32 whi = eW[s * 64 + wp * 16 + gid + 8][sub];
                float pm[4][4];
                #pragma unroll
                for (int nt = 0; nt < 4; nt++) {
                    float p0 = __expf(sc[s][nt][0]);
                    float p1 = __expf(sc[s][nt][1]);
                    float p2 = __expf(sc[s][nt][2]);
                    float p3 = __expf(sc[s][nt][3]);
                    int bp = nt * 8 + tig * 2;
                    float m0 = ((wlo >> bp) & 1u) ? p0 : 0.0f;
                    float m1 = ((wlo >> (bp + 1)) & 1u) ? p1 : 0.0f;
                    float m2 = ((whi >> bp) & 1u) ? p2 : 0.0f;
                    float m3 = ((whi >> (bp + 1)) & 1u) ? p3 : 0.0f;
                    sl[s] += m0 + m1; sh[s] += m2 + m3;
                    pm[nt][0] = m0; pm[nt][1] = m1; pm[nt][2] = m2; pm[nt][3] = m3;
                }
                #pragma unroll
                for (int kc = 0; kc < 2; kc++) {
                    int na = kc * 2, nb = kc * 2 + 1;
                    float h00 = bf16rt(pm[na][0]), h01 = bf16rt(pm[na][1]);
                    float h02 = bf16rt(pm[na][2]), h03 = bf16rt(pm[na][3]);
                    float h10 = bf16rt(pm[nb][0]), h11 = bf16rt(pm[nb][1]);
                    float h12 = bf16rt(pm[nb][2]), h13 = bf16rt(pm[nb][3]);
                    ph[s][kc][0] = cvt2(h01, h00);
                    ph[s][kc][1] = cvt2(h03, h02);
                    ph[s][kc][2] = cvt2(h11, h10);
                    ph[s][kc][3] = cvt2(h13, h12);
                    pl[s][kc][0] = cvt2(pm[na][1] - h01, pm[na][0] - h00);
                    pl[s][kc][1] = cvt2(pm[na][3] - h03, pm[na][2] - h02);
                    pl[s][kc][2] = cvt2(pm[nb][1] - h11, pm[nb][0] - h10);
                    pl[s][kc][3] = cvt2(pm[nb][3] - h13, pm[nb][2] - h12);
                }
            }
            #pragma unroll
            for (int kc = 0; kc < 2; kc++)
                #pragma unroll
                for (int vt = 0; vt < 4; vt++) {
                    int d = vt * 8 + gid;
                    uint4 vf = Vs4[d * 36 + (sub * 2 + kc) * 4 + tig];
                    mma16816(oc[0][vt], ph[0][kc], vf.x, vf.y);
                    mma16816(oc[0][vt], pl[0][kc], vf.x, vf.y);
                    mma16816(oc[0][vt], ph[0][kc], vf.z, vf.w);
                    mma16816(oc[1][vt], ph[1][kc], vf.x, vf.y);
                    mma16816(oc[1][vt], pl[1][kc], vf.x, vf.y);
                    mma16816(oc[1][vt], ph[1][kc], vf.z, vf.w);
                }
        }
    }

    #pragma unroll
    for (int s = 0; s < 2; s++) {
        float slo = sl[s], shi = sh[s];
        #pragma unroll
        for (int o = 1; o <= 2; o <<= 1) {
            slo += __shfl_xor_sync(0xffffffffu, slo, o);
            shi += __shfl_xor_sync(0xffffffffu, shi, o);
        }
        float invlo = 1.0f / slo;
        float invhi = 1.0f / shi;
        int nlo = i0 + s * 64 + wp * 16 + gid;
        int nhi = nlo + 8;
        size_t olo = ((size_t)(b * NNODE + nlo)) * DDIM + h * HDIM;
        size_t ohi = ((size_t)(b * NNODE + nhi)) * DDIM + h * HDIM;
        #pragma unroll
        for (int vt = 0; vt < 4; vt++) {
            int d = vt * 8 + tig * 2;
            *(float2*)&g_attn[olo + d] = make_float2(oc[s][vt][0] * invlo, oc[s][vt][1] * invlo);
            *(float2*)&g_attn[ohi + d] = make_float2(oc[s][vt][2] * invhi, oc[s][vt][3] * invhi);
        }
    }
}

// =====================================================================
// LAUNCH 4: O projection GEMM (fp32 out) — 64x64 tiles, 256 blocks
// (was 128x64/128 blocks: grid < SM count left occ at 12%, 32us measured)
// =====================================================================
__global__ void __launch_bounds__(256) k_gemmO(const float* __restrict__ A, const float* __restrict__ W,
                       const float* __restrict__ bias, float* __restrict__ OutF) {
    __shared__ __align__(16) u64   As2[16][66];
    __shared__ __align__(16) float Ws[16][68];
    int tid = threadIdx.x;
    int tx = tid & 15;       // col group: cols c0 + tx*4 + {0..3}
    int ty = tid >> 4;       // row group: rows m0 + ty*4 + {0..3}
    int m0 = blockIdx.x * 64, c0 = blockIdx.y * 64;
    int lkk = tid & 15, lm = tid >> 4;

    u64 acc[4][2];
    #pragma unroll
    for (int i = 0; i < 4; i++) { acc[i][0] = 0ull; acc[i][1] = 0ull; }

    for (int k0 = 0; k0 < DDIM; k0 += 16) {
        #pragma unroll
        for (int rr = 0; rr < 4; rr++) {
            int m = lm + 16 * rr;
            float v = A[(size_t)(m0 + m) * DDIM + k0 + lkk];
            As2[lkk][m] = pk2(v, v);
        }
        #pragma unroll
        for (int rr = 0; rr < 4; rr++) {
            int c = lm + 16 * rr;
            Ws[lkk][c] = W[(size_t)(c0 + c) * DDIM + k0 + lkk];
        }
        __syncthreads();
        #pragma unroll
        for (int kk = 0; kk < 16; kk++) {
            float4 w4 = *(const float4*)&Ws[kk][tx * 4];
            u64 w01 = pk2(w4.x, w4.y), w23 = pk2(w4.z, w4.w);
            const u64* arow = &As2[kk][ty * 4];
            ulonglong2 a01 = *(const ulonglong2*)&arow[0];
            ulonglong2 a23 = *(const ulonglong2*)&arow[2];
            acc[0][0] = ffma2(a01.x, w01, acc[0][0]);
            acc[0][1] = ffma2(a01.x, w23, acc[0][1]);
            acc[1][0] = ffma2(a01.y, w01, acc[1][0]);
            acc[1][1] = ffma2(a01.y, w23, acc[1][1]);
            acc[2][0] = ffma2(a23.x, w01, acc[2][0]);
            acc[2][1] = ffma2(a23.x, w23, acc[2][1]);
            acc[3][0] = ffma2(a23.y, w01, acc[3][0]);
            acc[3][1] = ffma2(a23.y, w23, acc[3][1]);
        }
        __syncthreads();
    }

    float4 b4 = *(const float4*)&bias[c0 + tx * 4];
    int c = c0 + tx * 4;
    #pragma unroll
    for (int ii = 0; ii < 4; ii++) {
        int m = m0 + ty * 4 + ii;
        float f0, f1, f2, f3;
        upk2(acc[ii][0], f0, f1);
        upk2(acc[ii][1], f2, f3);
        *(float4*)&OutF[(size_t)m * DDIM + c] =
            make_float4(f0 + b4.x, f1 + b4.y, f2 + b4.z, f3 + b4.w);
    }
}

// ---------------- launch (4 launches, single stream, graph-capturable) ----------------
extern "C" void kernel_launch(void* const* d_in, const int* in_sizes, int n_in,
                              void* d_out, int out_size) {
    (void)in_sizes; (void)n_in; (void)out_size;
    const float* x   = (const float*)d_in[0];
    const int*   ei  = (const int*)  d_in[1];
    const float* qw  = (const float*)d_in[2];
    const float* qb  = (const float*)d_in[3];
    const float* kw  = (const float*)d_in[4];
    const float* kb  = (const float*)d_in[5];
    const float* vw  = (const float*)d_in[6];
    const float* vb  = (const float*)d_in[7];
    const float* ow  = (const float*)d_in[8];
    const float* ob  = (const float*)d_in[9];
    const float* g1w = (const float*)d_in[10];
    const float* g1b = (const float*)d_in[11];
    const float* g2w = (const float*)d_in[12];
    const float* g2b = (const float*)d_in[13];

    float* out = (float*)d_out;
    float* outMask = out + (size_t)BB * NNODE * DDIM;

    u32 *pQh, *pQl, *pKi, *pVi;
    float* pAttn;
    cudaGetSymbolAddress((void**)&pQh, g_Qh);
    cudaGetSymbolAddress((void**)&pQl, g_Ql);
    cudaGetSymbolAddress((void**)&pKi, g_Ki);
    cudaGetSymbolAddress((void**)&pVi, g_Vi);
    cudaGetSymbolAddress((void**)&pAttn, g_attn);

    const float qscale = 0.17677669529663687f;  // 1/sqrt(32)

    k_pre1<<<768, 256>>>(x, g1w, g1b, g2w, g2b);
    k_pre2<<<642, 256>>>(x, ei, qw, qb, kw, kb, vw, vb,
                         pQh, pQl, pKi, pVi, qscale);
    k_attn<<<dim3(NNODE / 128, BB * HH), 128>>>(outMask);
    k_gemmO<<<dim3(BB * NNODE / 64, DDIM / 64), 256>>>(pAttn, ow, ob, out);
}

// round 14
// speedup vs baseline: 1.0606x; 1.0579x over previous
#include <cuda_runtime.h>
#include <cuda_bf16.h>
#include <cstdint>
#include <cstddef>

#define BB 2
#define NNODE 2048
#define DDIM 256
#define HH 8
#define HDIM 32
#define EEDGE 65536
#define KTOP 1024
#define NWRD (NNODE/32)   // 64 u32 words per adjacency row

typedef unsigned u32;
typedef unsigned long long u64;

// ---------------- packed f32x2 helpers ----------------
__device__ __forceinline__ u64 ffma2(u64 a, u64 b, u64 c) {
    u64 d; asm("fma.rn.f32x2 %0, %1, %2, %3;" : "=l"(d) : "l"(a), "l"(b), "l"(c)); return d;
}
__device__ __forceinline__ u64 pk2(float lo, float hi) {
    u64 d; asm("mov.b64 %0, {%1, %2};" : "=l"(d) : "f"(lo), "f"(hi)); return d;
}
__device__ __forceinline__ void upk2(u64 v, float& lo, float& hi) {
    asm("mov.b64 {%0, %1}, %2;" : "=f"(lo), "=f"(hi) : "l"(v));
}
__device__ __forceinline__ u32 cvt2(float hi, float lo) {
    u32 r; asm("cvt.rn.bf16x2.f32 %0, %1, %2;" : "=r"(r) : "f"(hi), "f"(lo)); return r;
}
__device__ __forceinline__ float bf16rt(float x) {
    return __bfloat162float(__float2bfloat16_rn(x));
}
__device__ __forceinline__ void mma16816(float c[4], const u32 a[4], u32 b0, u32 b1) {
    asm volatile(
        "mma.sync.aligned.m16n8k16.row.col.f32.bf16.bf16.f32 "
        "{%0,%1,%2,%3},{%4,%5,%6,%7},{%8,%9},{%0,%1,%2,%3};"
        : "+f"(c[0]), "+f"(c[1]), "+f"(c[2]), "+f"(c[3])
        : "r"(a[0]), "r"(a[1]), "r"(a[2]), "r"(a[3]), "r"(b0), "r"(b1));
}

// ---------------- scratch (device globals) ----------------
__device__ float g_topo[BB*NNODE];
__device__ u32   g_edge[NNODE*NWRD];
__device__ u32   g_colbits[BB*NWRD];
__device__ __nv_bfloat16 g_Qh[(size_t)BB*HH*NNODE*HDIM];
__device__ __nv_bfloat16 g_Ql[(size_t)BB*HH*NNODE*HDIM];
__device__ u32 g_Ki[(size_t)BB*HH*NNODE*32];
__device__ u32 g_Vi[(size_t)BB*HH*HDIM*2048];
__device__ float g_attn[(size_t)BB*NNODE*DDIM];

// ---------------- zero edge bits ----------------
__global__ void k_zero() {
    int i = blockIdx.x * blockDim.x + threadIdx.x;
    if (i < NNODE*NWRD) g_edge[i] = 0u;
}

// ---------------- scatter edges into bitmask ----------------
__global__ void k_scatter(const int* __restrict__ ei) {
    int e = blockIdx.x * blockDim.x + threadIdx.x;
    if (e >= EEDGE) return;
    int r = ei[e];
    int c = ei[EEDGE + e];
    atomicOr(&g_edge[r * NWRD + (c >> 5)], 1u << (c & 31));
}

// ---------------- topo scores (f32x2 packed) ----------------
__global__ void __launch_bounds__(128) k_topo(const float* __restrict__ x,
                       const float* __restrict__ g1w, const float* __restrict__ g1b,
                       const float* __restrict__ g2w, const float* __restrict__ g2b) {
    __shared__ __align__(16) float xs[8][DDIM];
    __shared__ float rs[8][4];
    int t = threadIdx.x;
    int base = blockIdx.x * 8;

    const float4* xv = (const float4*)(x + (size_t)base * DDIM);
    float4* xsv = (float4*)&xs[0][0];
    #pragma unroll
    for (int r = 0; r < 4; r++) xsv[t + r * 128] = xv[t + r * 128];
    __syncthreads();

    u64 acc[8];
    #pragma unroll
    for (int nn = 0; nn < 8; nn++) acc[nn] = 0ull;

    const ulonglong2* wrow = (const ulonglong2*)(g1w + (size_t)t * DDIM);
    #pragma unroll 4
    for (int k4 = 0; k4 < DDIM/4; k4++) {
        ulonglong2 wv = wrow[k4];
        #pragma unroll
        for (int nn = 0; nn < 8; nn++) {
            ulonglong2 xp = ((const ulonglong2*)xs[nn])[k4];
            acc[nn] = ffma2(wv.x, xp.x, acc[nn]);
            acc[nn] = ffma2(wv.y, xp.y, acc[nn]);
        }
    }
    float b1 = g1b[t];
    float w2s = g2w[t];
    float res[8];
    #pragma unroll
    for (int nn = 0; nn < 8; nn++) {
        float lo, hi; upk2(acc[nn], lo, hi);
        float h = fmaxf(lo + hi + b1, 0.0f);
        res[nn] = h * w2s;
    }
    int lane = t & 31, wrp = t >> 5;
    #pragma unroll
    for (int nn = 0; nn < 8; nn++) {
        float v = res[nn];
        #pragma unroll
        for (int o = 16; o > 0; o >>= 1) v += __shfl_down_sync(0xffffffffu, v, o);
        if (lane == 0) rs[nn][wrp] = v;
    }
    __syncthreads();
    if (t < 8) {
        float v = rs[t][0] + rs[t][1] + rs[t][2] + rs[t][3];
        g_topo[base + t] = v + g2b[0];
    }
}

// ---------------- exact top-k: radix select with parallel threshold find ----------------
__global__ void __launch_bounds__(256) k_topk() {
    __shared__ u32 keys[NNODE];
    __shared__ u32 hist[256];
    __shared__ u32 sb[256];
    __shared__ u32 scn[256];
    __shared__ u32 sh_prefix, sh_remain;
    int b = blockIdx.x;
    int t = threadIdx.x;  // 256 threads

    if (t < NWRD) g_colbits[b * NWRD + t] = 0u;

    for (int i = t; i < NNODE; i += 256) {
        u32 u = __float_as_uint(g_topo[b * NNODE + i]);
        u = (u & 0x80000000u) ? ~u : (u | 0x80000000u);  // monotone ascending
        keys[i] = u;
    }
    u32 prefix = 0, remain = KTOP;
    __syncthreads();

    for (int shift = 24; shift >= 0; shift -= 8) {
        hist[t] = 0;
        __syncthreads();
        for (int i = t; i < NNODE; i += 256) {
            u32 k = keys[i];
            bool in_group = (shift == 24) || ((k >> (shift + 8)) == prefix);
            if (in_group) atomicAdd(&hist[(k >> shift) & 255], 1u);
        }
        __syncthreads();
        sb[t] = hist[t];
        __syncthreads();
        for (int ofs = 1; ofs < 256; ofs <<= 1) {
            u32 add = (t + ofs < 256) ? sb[t + ofs] : 0u;
            __syncthreads();
            sb[t] += add;
            __syncthreads();
        }
        u32 above = (t == 255) ? 0u : sb[t + 1];
        if (sb[t] >= remain && above < remain) {
            sh_prefix = (prefix << 8) | (u32)t;
            sh_remain = remain - above;
        }
        __syncthreads();
        prefix = sh_prefix;
        remain = sh_remain;
        __syncthreads();
    }
    u32 T = prefix;

    u32 cnt = 0;
    #pragma unroll
    for (int u = 0; u < 8; u++) if (keys[t * 8 + u] == T) cnt++;
    scn[t] = cnt;
    __syncthreads();
    for (int ofs = 1; ofs < 256; ofs <<= 1) {
        u32 v = scn[t];
        u32 add = (t >= ofs) ? scn[t - ofs] : 0u;
        __syncthreads();
        scn[t] = v + add;
        __syncthreads();
    }
    u32 taken = scn[t] - cnt;
    u32 byte = 0;
    #pragma unroll
    for (int u = 0; u < 8; u++) {
        u32 k = keys[t * 8 + u];
        bool m = false;
        if (k > T) m = true;
        else if (k == T) { if (taken < remain) m = true; taken++; }
        if (m) byte |= (1u << u);
    }
    atomicOr(&g_colbits[b * NWRD + (t >> 2)], byte << ((t & 3) * 8));
}

// ---------------- fused QKV GEMM (f32x2 core, reg-prefetch pipelined) ----------------
__global__ void __launch_bounds__(256) k_gemmQKV(
        const float* __restrict__ A,
        const float* __restrict__ qw, const float* __restrict__ qb,
        const float* __restrict__ kw, const float* __restrict__ kb,
        const float* __restrict__ vw, const float* __restrict__ vb,
        u32* __restrict__ Qh, u32* __restrict__ Ql,
        u32* __restrict__ Ki, u32* __restrict__ Vi, float qscale) {
    __shared__ __align__(16) u64   As2[16][130];
    __shared__ __align__(16) float Ws[16][68];
    int mode = blockIdx.z;
    const float* W    = (mode == 0) ? qw : (mode == 1) ? kw : vw;
    const float* bias = (mode == 0) ? qb : (mode == 1) ? kb : vb;
    float scale = (mode == 0) ? qscale : 1.0f;

    int tid = threadIdx.x;
    int tx = tid & 15;
    int rg = tid >> 4;
    int m0 = blockIdx.x * 128, c0 = blockIdx.y * 64;
    int lkk = tid & 15, lm = tid >> 4;

    u64 acc[8][2];
    #pragma unroll
    for (int i = 0; i < 8; i++) { acc[i][0] = 0ull; acc[i][1] = 0ull; }

    // prefetch first k-tile into regs
    float a_pre[8], w_pre[4];
    #pragma unroll
    for (int rr = 0; rr < 8; rr++)
        a_pre[rr] = A[(size_t)(m0 + lm + 16 * rr) * DDIM + lkk];
    #pragma unroll
    for (int rr = 0; rr < 4; rr++)
        w_pre[rr] = W[(size_t)(c0 + lm + 16 * rr) * DDIM + lkk];

    for (int k0 = 0; k0 < DDIM; k0 += 16) {
        #pragma unroll
        for (int rr = 0; rr < 8; rr++) As2[lkk][lm + 16 * rr] = pk2(a_pre[rr], a_pre[rr]);
        #pragma unroll
        for (int rr = 0; rr < 4; rr++) Ws[lkk][lm + 16 * rr] = w_pre[rr];
        __syncthreads();
        // issue next tile's gmem loads; latency hides under compute below
        if (k0 + 16 < DDIM) {
            #pragma unroll
            for (int rr = 0; rr < 8; rr++)
                a_pre[rr] = A[(size_t)(m0 + lm + 16 * rr) * DDIM + k0 + 16 + lkk];
            #pragma unroll
            for (int rr = 0; rr < 4; rr++)
                w_pre[rr] = W[(size_t)(c0 + lm + 16 * rr) * DDIM + k0 + 16 + lkk];
        }
        #pragma unroll
        for (int kk = 0; kk < 16; kk++) {
            float4 w4 = *(const float4*)&Ws[kk][tx * 4];
            u64 w01 = pk2(w4.x, w4.y), w23 = pk2(w4.z, w4.w);
            const u64* arow = &As2[kk][rg * 8];
            #pragma unroll
            for (int ii = 0; ii < 8; ii += 2) {
                ulonglong2 a2 = *(const ulonglong2*)&arow[ii];
                acc[ii][0]     = ffma2(a2.x, w01, acc[ii][0]);
                acc[ii][1]     = ffma2(a2.x, w23, acc[ii][1]);
                acc[ii + 1][0] = ffma2(a2.y, w01, acc[ii + 1][0]);
                acc[ii + 1][1] = ffma2(a2.y, w23, acc[ii + 1][1]);
            }
        }
        __syncthreads();
    }

    float4 b4 = *(const float4*)&bias[c0 + tx * 4];
    int c = c0 + tx * 4;                 // 4 consecutive cols (same head)
    int h = (c >> 5) & 7, cw = c & 31;
    int bb = m0 >> 11;
    int n0 = (m0 & 2047) + rg * 8;
    int bh = bb * HH + h;

    if (mode == 2) {
        float vals[8][4];
        #pragma unroll
        for (int ii = 0; ii < 8; ii++) {
            float f0, f1, f2, f3;
            upk2(acc[ii][0], f0, f1);
            upk2(acc[ii][1], f2, f3);
            vals[ii][0] = f0 + b4.x; vals[ii][1] = f1 + b4.y;
            vals[ii][2] = f2 + b4.z; vals[ii][3] = f3 + b4.w;
        }
        int w0v = n0 >> 1;
        int jt = w0v >> 6;
        int s8 = (w0v & 63) >> 3;
        int slot = (w0v >> 2) & 1;
        #pragma unroll
        for (int jj = 0; jj < 4; jj++) {
            int d = cw + jj;
            size_t dbase = ((size_t)bh * HDIM + d) * 2048;
            #pragma unroll
            for (int p = 0; p < 4; p++) {
                float v0 = vals[2*p][jj], v1 = vals[2*p+1][jj];
                float h0 = bf16rt(v0), h1 = bf16rt(v1);
                size_t ub = dbase + (size_t)(jt * 32 + s8 * 4 + p) * 4;
                Vi[ub + slot]     = cvt2(h1, h0);
                Vi[ub + slot + 2] = cvt2(v1 - h1, v0 - h0);
            }
        }
    } else if (mode == 1) {
        int w0 = cw >> 1;
        int kc = w0 >> 3, t0 = w0 & 7;
        int u0 = kc * 4 + (t0 & 3);
        int s = t0 >> 2;
        #pragma unroll
        for (int ii = 0; ii < 8; ii++) {
            float f0, f1, f2, f3;
            upk2(acc[ii][0], f0, f1);
            upk2(acc[ii][1], f2, f3);
            f0 += b4.x; f1 += b4.y; f2 += b4.z; f3 += b4.w;
            float h0 = bf16rt(f0), h1 = bf16rt(f1), h2 = bf16rt(f2), h3 = bf16rt(f3);
            int n = n0 + ii;
            size_t rb = ((size_t)bh * NNODE + n) * 32;
            Ki[rb + u0*4 + s]           = cvt2(h1, h0);
            Ki[rb + (u0+1)*4 + s]       = cvt2(h3, h2);
            Ki[rb + u0*4 + s + 2]       = cvt2(f1 - h1, f0 - h0);
            Ki[rb + (u0+1)*4 + s + 2]   = cvt2(f3 - h3, f2 - h2);
        }
    } else {
        #pragma unroll
        for (int ii = 0; ii < 8; ii++) {
            float f0, f1, f2, f3;
            upk2(acc[ii][0], f0, f1);
            upk2(acc[ii][1], f2, f3);
            f0 = (f0 + b4.x) * scale; f1 = (f1 + b4.y) * scale;
            f2 = (f2 + b4.z) * scale; f3 = (f3 + b4.w) * scale;
            float h0 = bf16rt(f0), h1 = bf16rt(f1), h2 = bf16rt(f2), h3 = bf16rt(f3);
            int n = n0 + ii;
            size_t widx = ((size_t)bh * NNODE + n) * (HDIM/2) + (cw >> 1);
            *(uint2*)&Qh[widx] = make_uint2(cvt2(h1, h0), cvt2(h3, h2));
            *(uint2*)&Ql[widx] = make_uint2(cvt2(f1 - h1, f0 - h0), cvt2(f3 - h3, f2 - h2));
        }
    }
}

// ---------------- fused masked attention + mask writeback ----------------
__global__ void __launch_bounds__(128) k_attn(float* __restrict__ outMask) {
    __shared__ __align__(16) uint4 Ks4[128 * 12];
    __shared__ __align__(16) uint4 Vs4[32 * 36];
    __shared__ __align__(16) u32 eW[128][4];

    int tid = threadIdx.x;
    int wp = tid >> 5, lane = tid & 31;
    int gid = lane >> 2, tig = lane & 3;
    int bh = blockIdx.y, b = bh >> 3, h = bh & 7;
    int i0 = blockIdx.x * 128;

    const u32* gqh = (const u32*)g_Qh;
    const u32* gql = (const u32*)g_Ql;
    const uint4* gKi = (const uint4*)g_Ki;
    const uint4* gVi = (const uint4*)g_Vi;
    const uint4* gE  = (const uint4*)g_edge;

    u32 qh[2][2][4], ql[2][2][4];
    #pragma unroll
    for (int s = 0; s < 2; s++) {
        size_t blo = ((size_t)bh * NNODE + i0 + s * 64 + wp * 16 + gid) * 16;
        size_t bhi = blo + 8 * 16;
        #pragma unroll
        for (int kc = 0; kc < 2; kc++) {
            qh[s][kc][0] = gqh[blo + kc*8 + tig];
            qh[s][kc][1] = gqh[bhi + kc*8 + tig];
            qh[s][kc][2] = gqh[blo + kc*8 + tig + 4];
            qh[s][kc][3] = gqh[bhi + kc*8 + tig + 4];
            ql[s][kc][0] = gql[blo + kc*8 + tig];
            ql[s][kc][1] = gql[bhi + kc*8 + tig];
            ql[s][kc][2] = gql[blo + kc*8 + tig + 4];
            ql[s][kc][3] = gql[bhi + kc*8 + tig + 4];
        }
    }

    float oc[2][4][4];
    #pragma unroll
    for (int s = 0; s < 2; s++)
        #pragma unroll
        for (int vt = 0; vt < 4; vt++)
            #pragma unroll
            for (int e = 0; e < 4; e++) oc[s][vt][e] = 0.0f;
    float sl[2] = {0.0f, 0.0f}, sh[2] = {0.0f, 0.0f};

    for (int j0 = 0; j0 < NNODE; j0 += 128) {
        __syncthreads();
        for (int idx = tid; idx < 1024; idx += 128) {
            int r = idx >> 3, g = idx & 7;
            Ks4[r * 12 + g] = gKi[((size_t)bh * NNODE + j0 + r) * 8 + g];
        }
        for (int idx = tid; idx < 1024; idx += 128) {
            int d = idx >> 5, gv = idx & 31;
            Vs4[d * 36 + gv] = gVi[((size_t)bh * HDIM + d) * 512 + (j0 >> 7) * 32 + gv];
        }
        {
            uint4 cb = *(const uint4*)&g_colbits[b * NWRD + (j0 >> 5)];
            uint4 e4 = gE[(size_t)(i0 + tid) * 16 + (j0 >> 7)];
            eW[tid][0] = e4.x | cb.x; eW[tid][1] = e4.y | cb.y;
            eW[tid][2] = e4.z | cb.z; eW[tid][3] = e4.w | cb.w;
        }
        __syncthreads();

        // coalesced sparse_mask writeback (streaming)
        {
            #pragma unroll 8
            for (int rr = 0; rr < 32; rr++) {
                int r = wp + rr * 4;
                u32 bits = eW[r][lane >> 3];
                int bo = (lane & 7) * 4;
                float4 f;
                f.x = (bits >> (bo + 0)) & 1u ? 1.0f : 0.0f;
                f.y = (bits >> (bo + 1)) & 1u ? 1.0f : 0.0f;
                f.z = (bits >> (bo + 2)) & 1u ? 1.0f : 0.0f;
                f.w = (bits >> (bo + 3)) & 1u ? 1.0f : 0.0f;
                __stcs((float4*)(outMask + ((size_t)bh * NNODE + i0 + r) * NNODE + j0) + lane, f);
            }
        }

        #pragma unroll 1
        for (int sub = 0; sub < 4; sub++) {
            float sc[2][4][4];
            #pragma unroll
            for (int s = 0; s < 2; s++)
                #pragma unroll
                for (int nt = 0; nt < 4; nt++)
                    #pragma unroll
                    for (int e = 0; e < 4; e++) sc[s][nt][e] = 0.0f;
            #pragma unroll
            for (int kc = 0; kc < 2; kc++)
                #pragma unroll
                for (int nt = 0; nt < 4; nt++) {
                    int jr = sub * 32 + nt * 8 + gid;
                    uint4 kf = Ks4[jr * 12 + kc * 4 + tig];
                    mma16816(sc[0][nt], qh[0][kc], kf.x, kf.y);
                    mma16816(sc[0][nt], ql[0][kc], kf.x, kf.y);
                    mma16816(sc[0][nt], qh[0][kc], kf.z, kf.w);
                    mma16816(sc[1][nt], qh[1][kc], kf.x, kf.y);
                    mma16816(sc[1][nt], ql[1][kc], kf.x, kf.y);
                    mma16816(sc[1][nt], qh[1][kc], kf.z, kf.w);
                }
            u32 ph[2][2][4], pl[2][2][4];
            #pragma unroll
            for (int s = 0; s < 2; s++) {
                u32 wlo = eW[s * 64 + wp * 16 + gid][sub];
                u32 whi = eW[s * 64 + wp * 16 + gid + 8][sub];
                float pm[4][4];
                #pragma unroll
                for (int nt = 0; nt < 4; nt++) {
                    float p0 = __expf(sc[s][nt][0]);
                    float p1 = __expf(sc[s][nt][1]);
                    float p2 = __expf(sc[s][nt][2]);
                    float p3 = __expf(sc[s][nt][3]);
                    int bp = nt * 8 + tig * 2;
                    float m0 = ((wlo >> bp) & 1u) ? p0 : 0.0f;
                    float m1 = ((wlo >> (bp + 1)) & 1u) ? p1 : 0.0f;
                    float m2 = ((whi >> bp) & 1u) ? p2 : 0.0f;
                    float m3 = ((whi >> (bp + 1)) & 1u) ? p3 : 0.0f;
                    sl[s] += m0 + m1; sh[s] += m2 + m3;
                    pm[nt][0] = m0; pm[nt][1] = m1; pm[nt][2] = m2; pm[nt][3] = m3;
                }
                #pragma unroll
                for (int kc = 0; kc < 2; kc++) {
                    int na = kc * 2, nb = kc * 2 + 1;
                    float h00 = bf16rt(pm[na][0]), h01 = bf16rt(pm[na][1]);
                    float h02 = bf16rt(pm[na][2]), h03 = bf16rt(pm[na][3]);
                    float h10 = bf16rt(pm[nb][0]), h11 = bf16rt(pm[nb][1]);
                    float h12 = bf16rt(pm[nb][2]), h13 = bf16rt(pm[nb][3]);
                    ph[s][kc][0] = cvt2(h01, h00);
                    ph[s][kc][1] = cvt2(h03, h02);
                    ph[s][kc][2] = cvt2(h11, h10);
                    ph[s][kc][3] = cvt2(h13, h12);
                    pl[s][kc][0] = cvt2(pm[na][1] - h01, pm[na][0] - h00);
                    pl[s][kc][1] = cvt2(pm[na][3] - h03, pm[na][2] - h02);
                    pl[s][kc][2] = cvt2(pm[nb][1] - h11, pm[nb][0] - h10);
                    pl[s][kc][3] = cvt2(pm[nb][3] - h13, pm[nb][2] - h12);
                }
            }
            #pragma unroll
            for (int kc = 0; kc < 2; kc++)
                #pragma unroll
                for (int vt = 0; vt < 4; vt++) {
                    int d = vt * 8 + gid;
                    uint4 vf = Vs4[d * 36 + (sub * 2 + kc) * 4 + tig];
                    mma16816(oc[0][vt], ph[0][kc], vf.x, vf.y);
                    mma16816(oc[0][vt], pl[0][kc], vf.x, vf.y);
                    mma16816(oc[0][vt], ph[0][kc], vf.z, vf.w);
                    mma16816(oc[1][vt], ph[1][kc], vf.x, vf.y);
                    mma16816(oc[1][vt], pl[1][kc], vf.x, vf.y);
                    mma16816(oc[1][vt], ph[1][kc], vf.z, vf.w);
                }
        }
    }

    #pragma unroll
    for (int s = 0; s < 2; s++) {
        float slo = sl[s], shi = sh[s];
        #pragma unroll
        for (int o = 1; o <= 2; o <<= 1) {
            slo += __shfl_xor_sync(0xffffffffu, slo, o);
            shi += __shfl_xor_sync(0xffffffffu, shi, o);
        }
        float invlo = 1.0f / slo;
        float invhi = 1.0f / shi;
        int nlo = i0 + s * 64 + wp * 16 + gid;
        int nhi = nlo + 8;
        size_t olo = ((size_t)(b * NNODE + nlo)) * DDIM + h * HDIM;
        size_t ohi = ((size_t)(b * NNODE + nhi)) * DDIM + h * HDIM;
        #pragma unroll
        for (int vt = 0; vt < 4; vt++) {
            int d = vt * 8 + tig * 2;
            *(float2*)&g_attn[olo + d] = make_float2(oc[s][vt][0] * invlo, oc[s][vt][1] * invlo);
            *(float2*)&g_attn[ohi + d] = make_float2(oc[s][vt][2] * invhi, oc[s][vt][3] * invhi);
        }
    }
}

// ---------------- O projection GEMM: 64x64 tiles, reg-prefetch pipelined ----------------
__global__ void __launch_bounds__(256) k_gemmO(const float* __restrict__ A, const float* __restrict__ W,
                       const float* __restrict__ bias, float* __restrict__ OutF) {
    __shared__ __align__(16) u64   As2[16][66];
    __shared__ __align__(16) float Ws[16][68];
    int tid = threadIdx.x;
    int tx = tid & 15;
    int ty = tid >> 4;
    int m0 = blockIdx.x * 64, c0 = blockIdx.y * 64;
    int lkk = tid & 15, lm = tid >> 4;

    u64 acc[4][2];
    #pragma unroll
    for (int i = 0; i < 4; i++) { acc[i][0] = 0ull; acc[i][1] = 0ull; }

    float a_pre[4], w_pre[4];
    #pragma unroll
    for (int rr = 0; rr < 4; rr++) {
        a_pre[rr] = A[(size_t)(m0 + lm + 16 * rr) * DDIM + lkk];
        w_pre[rr] = W[(size_t)(c0 + lm + 16 * rr) * DDIM + lkk];
    }

    for (int k0 = 0; k0 < DDIM; k0 += 16) {
        #pragma unroll
        for (int rr = 0; rr < 4; rr++) {
            As2[lkk][lm + 16 * rr] = pk2(a_pre[rr], a_pre[rr]);
            Ws[lkk][lm + 16 * rr] = w_pre[rr];
        }
        __syncthreads();
        if (k0 + 16 < DDIM) {
            #pragma unroll
            for (int rr = 0; rr < 4; rr++) {
                a_pre[rr] = A[(size_t)(m0 + lm + 16 * rr) * DDIM + k0 + 16 + lkk];
                w_pre[rr] = W[(size_t)(c0 + lm + 16 * rr) * DDIM + k0 + 16 + lkk];
            }
        }
        #pragma unroll
        for (int kk = 0; kk < 16; kk++) {
            float4 w4 = *(const float4*)&Ws[kk][tx * 4];
            u64 w01 = pk2(w4.x, w4.y), w23 = pk2(w4.z, w4.w);
            const u64* arow = &As2[kk][ty * 4];
            ulonglong2 a01 = *(const ulonglong2*)&arow[0];
            ulonglong2 a23 = *(const ulonglong2*)&arow[2];
            acc[0][0] = ffma2(a01.x, w01, acc[0][0]);
            acc[0][1] = ffma2(a01.x, w23, acc[0][1]);
            acc[1][0] = ffma2(a01.y, w01, acc[1][0]);
            acc[1][1] = ffma2(a01.y, w23, acc[1][1]);
            acc[2][0] = ffma2(a23.x, w01, acc[2][0]);
            acc[2][1] = ffma2(a23.x, w23, acc[2][1]);
            acc[3][0] = ffma2(a23.y, w01, acc[3][0]);
            acc[3][1] = ffma2(a23.y, w23, acc[3][1]);
        }
        __syncthreads();
    }

    float4 b4 = *(const float4*)&bias[c0 + tx * 4];
    int c = c0 + tx * 4;
    #pragma unroll
    for (int ii = 0; ii < 4; ii++) {
        int m = m0 + ty * 4 + ii;
        float f0, f1, f2, f3;
        upk2(acc[ii][0], f0, f1);
        upk2(acc[ii][1], f2, f3);
        *(float4*)&OutF[(size_t)m * DDIM + c] =
            make_float4(f0 + b4.x, f1 + b4.y, f2 + b4.z, f3 + b4.w);
    }
}

// ---------------- launch (single stream; graph-capturable) ----------------
extern "C" void kernel_launch(void* const* d_in, const int* in_sizes, int n_in,
                              void* d_out, int out_size) {
    (void)in_sizes; (void)n_in; (void)out_size;
    const float* x   = (const float*)d_in[0];
    const int*   ei  = (const int*)  d_in[1];
    const float* qw  = (const float*)d_in[2];
    const float* qb  = (const float*)d_in[3];
    const float* kw  = (const float*)d_in[4];
    const float* kb  = (const float*)d_in[5];
    const float* vw  = (const float*)d_in[6];
    const float* vb  = (const float*)d_in[7];
    const float* ow  = (const float*)d_in[8];
    const float* ob  = (const float*)d_in[9];
    const float* g1w = (const float*)d_in[10];
    const float* g1b = (const float*)d_in[11];
    const float* g2w = (const float*)d_in[12];
    const float* g2b = (const float*)d_in[13];

    float* out = (float*)d_out;
    float* outMask = out + (size_t)BB * NNODE * DDIM;

    u32 *pQh, *pQl, *pKi, *pVi;
    float* pAttn;
    cudaGetSymbolAddress((void**)&pQh, g_Qh);
    cudaGetSymbolAddress((void**)&pQl, g_Ql);
    cudaGetSymbolAddress((void**)&pKi, g_Ki);
    cudaGetSymbolAddress((void**)&pVi, g_Vi);
    cudaGetSymbolAddress((void**)&pAttn, g_attn);

    const float qscale = 0.17677669529663687f;  // 1/sqrt(32)

    k_zero<<<512, 256>>>();
    k_scatter<<<EEDGE / 256, 256>>>(ei);
    k_topo<<<BB * NNODE / 8, 128>>>(x, g1w, g1b, g2w, g2b);
    k_topk<<<BB, 256>>>();

    dim3 qkvgrid(BB * NNODE / 128, DDIM / 64, 3);
    k_gemmQKV<<<qkvgrid, 256>>>(x, qw, qb, kw, kb, vw, vb,
                                pQh, pQl, pKi, pVi, qscale);

    k_attn<<<dim3(NNODE / 128, BB * HH), 128>>>(outMask);

    k_gemmO<<<dim3(BB * NNODE / 64, DDIM / 64), 256>>>(pAttn, ow, ob, out);
}

// round 15
// speedup vs baseline: 1.0697x; 1.0086x over previous
#include <cuda_runtime.h>
#include <cuda_bf16.h>
#include <cstdint>
#include <cstddef>

#define BB 2
#define NNODE 2048
#define DDIM 256
#define HH 8
#define HDIM 32
#define EEDGE 65536
#define KTOP 1024
#define NWRD (NNODE/32)   // 64 u32 words per adjacency row

typedef unsigned u32;
typedef unsigned long long u64;

// ---------------- packed f32x2 helpers ----------------
__device__ __forceinline__ u64 ffma2(u64 a, u64 b, u64 c) {
    u64 d; asm("fma.rn.f32x2 %0, %1, %2, %3;" : "=l"(d) : "l"(a), "l"(b), "l"(c)); return d;
}
__device__ __forceinline__ u64 pk2(float lo, float hi) {
    u64 d; asm("mov.b64 %0, {%1, %2};" : "=l"(d) : "f"(lo), "f"(hi)); return d;
}
__device__ __forceinline__ void upk2(u64 v, float& lo, float& hi) {
    asm("mov.b64 {%0, %1}, %2;" : "=f"(lo), "=f"(hi) : "l"(v));
}
__device__ __forceinline__ u32 cvt2(float hi, float lo) {
    u32 r; asm("cvt.rn.bf16x2.f32 %0, %1, %2;" : "=r"(r) : "f"(hi), "f"(lo)); return r;
}
__device__ __forceinline__ float bf16rt(float x) {
    return __bfloat162float(__float2bfloat16_rn(x));
}
__device__ __forceinline__ void mma16816(float c[4], const u32 a[4], u32 b0, u32 b1) {
    asm volatile(
        "mma.sync.aligned.m16n8k16.row.col.f32.bf16.bf16.f32 "
        "{%0,%1,%2,%3},{%4,%5,%6,%7},{%8,%9},{%0,%1,%2,%3};"
        : "+f"(c[0]), "+f"(c[1]), "+f"(c[2]), "+f"(c[3])
        : "r"(a[0]), "r"(a[1]), "r"(a[2]), "r"(a[3]), "r"(b0), "r"(b1));
}
__device__ __forceinline__ void cpa16(void* sptr, const void* gptr) {
    u32 sa = (u32)__cvta_generic_to_shared(sptr);
    asm volatile("cp.async.cg.shared.global [%0], [%1], 16;" :: "r"(sa), "l"(gptr) : "memory");
}
#define CP_COMMIT() asm volatile("cp.async.commit_group;" ::: "memory")
#define CP_WAIT1()  asm volatile("cp.async.wait_group 1;" ::: "memory")

// ---------------- scratch (device globals) ----------------
__device__ float g_topo[BB*NNODE];
__device__ u32   g_edge[NNODE*NWRD];
__device__ u32   g_colbits[BB*NWRD];
__device__ __nv_bfloat16 g_Qh[(size_t)BB*HH*NNODE*HDIM];
__device__ __nv_bfloat16 g_Ql[(size_t)BB*HH*NNODE*HDIM];
__device__ u32 g_Ki[(size_t)BB*HH*NNODE*32];
__device__ u32 g_Vi[(size_t)BB*HH*HDIM*2048];
__device__ float g_attn[(size_t)BB*NNODE*DDIM];

// ---------------- zero edge bits ----------------
__global__ void k_zero() {
    int i = blockIdx.x * blockDim.x + threadIdx.x;
    if (i < NNODE*NWRD) g_edge[i] = 0u;
}

// ---------------- scatter edges into bitmask ----------------
__global__ void k_scatter(const int* __restrict__ ei) {
    int e = blockIdx.x * blockDim.x + threadIdx.x;
    if (e >= EEDGE) return;
    int r = ei[e];
    int c = ei[EEDGE + e];
    atomicOr(&g_edge[r * NWRD + (c >> 5)], 1u << (c & 31));
}

// ---------------- topo scores (f32x2 packed) ----------------
__global__ void __launch_bounds__(128) k_topo(const float* __restrict__ x,
                       const float* __restrict__ g1w, const float* __restrict__ g1b,
                       const float* __restrict__ g2w, const float* __restrict__ g2b) {
    __shared__ __align__(16) float xs[8][DDIM];
    __shared__ float rs[8][4];
    int t = threadIdx.x;
    int base = blockIdx.x * 8;

    const float4* xv = (const float4*)(x + (size_t)base * DDIM);
    float4* xsv = (float4*)&xs[0][0];
    #pragma unroll
    for (int r = 0; r < 4; r++) xsv[t + r * 128] = xv[t + r * 128];
    __syncthreads();

    u64 acc[8];
    #pragma unroll
    for (int nn = 0; nn < 8; nn++) acc[nn] = 0ull;

    const ulonglong2* wrow = (const ulonglong2*)(g1w + (size_t)t * DDIM);
    #pragma unroll 4
    for (int k4 = 0; k4 < DDIM/4; k4++) {
        ulonglong2 wv = wrow[k4];
        #pragma unroll
        for (int nn = 0; nn < 8; nn++) {
            ulonglong2 xp = ((const ulonglong2*)xs[nn])[k4];
            acc[nn] = ffma2(wv.x, xp.x, acc[nn]);
            acc[nn] = ffma2(wv.y, xp.y, acc[nn]);
        }
    }
    float b1 = g1b[t];
    float w2s = g2w[t];
    float res[8];
    #pragma unroll
    for (int nn = 0; nn < 8; nn++) {
        float lo, hi; upk2(acc[nn], lo, hi);
        float h = fmaxf(lo + hi + b1, 0.0f);
        res[nn] = h * w2s;
    }
    int lane = t & 31, wrp = t >> 5;
    #pragma unroll
    for (int nn = 0; nn < 8; nn++) {
        float v = res[nn];
        #pragma unroll
        for (int o = 16; o > 0; o >>= 1) v += __shfl_down_sync(0xffffffffu, v, o);
        if (lane == 0) rs[nn][wrp] = v;
    }
    __syncthreads();
    if (t < 8) {
        float v = rs[t][0] + rs[t][1] + rs[t][2] + rs[t][3];
        g_topo[base + t] = v + g2b[0];
    }
}

// ---------------- exact top-k: radix select, warp-shuffle scans ----------------
__global__ void __launch_bounds__(256) k_topk() {
    __shared__ u32 keys[NNODE];
    __shared__ u32 hist[256];
    __shared__ u32 ws[8];
    __shared__ u32 sh_prefix, sh_remain;
    int b = blockIdx.x;
    int t = threadIdx.x;  // 256 threads
    int lane = t & 31, wid = t >> 5;

    if (t < NWRD) g_colbits[b * NWRD + t] = 0u;

    for (int i = t; i < NNODE; i += 256) {
        u32 u = __float_as_uint(g_topo[b * NNODE + i]);
        u = (u & 0x80000000u) ? ~u : (u | 0x80000000u);  // monotone ascending
        keys[i] = u;
    }
    u32 prefix = 0, remain = KTOP;

    for (int shift = 24; shift >= 0; shift -= 8) {
        hist[t] = 0;
        __syncthreads();                 // keys ready (1st pass) + hist cleared + prev sh_* consumed
        for (int i = t; i < NNODE; i += 256) {
            u32 k = keys[i];
            bool in_group = (shift == 24) || ((k >> (shift + 8)) == prefix);
            if (in_group) atomicAdd(&hist[(k >> shift) & 255], 1u);
        }
        __syncthreads();
        u32 myh = hist[t];
        // warp inclusive SUFFIX scan (sum over lanes >= lane)
        u32 v = myh;
        #pragma unroll
        for (int o = 1; o < 32; o <<= 1) {
            u32 n = __shfl_down_sync(0xffffffffu, v, o);
            if (lane + o < 32) v += n;
        }
        if (lane == 0) ws[wid] = v;      // warp total
        __syncthreads();
        u32 add = 0;
        #pragma unroll
        for (int w = 0; w < 8; w++) add += (w > wid) ? ws[w] : 0u;
        u32 sbv = v + add;               // suffix sum from bucket t
        u32 above = sbv - myh;           // suffix sum from bucket t+1
        if (sbv >= remain && above < remain) {
            sh_prefix = (prefix << 8) | (u32)t;
            sh_remain = remain - above;
        }
        __syncthreads();
        prefix = sh_prefix;
        remain = sh_remain;
    }
    u32 T = prefix;  // KTOP-th largest key; take `remain` of the ==T set in index order

    u32 cnt = 0;
    #pragma unroll
    for (int u = 0; u < 8; u++) if (keys[t * 8 + u] == T) cnt++;
    // exclusive prefix (index order): warp inclusive prefix + cross-warp combine
    u32 pv = cnt;
    #pragma unroll
    for (int o = 1; o < 32; o <<= 1) {
        u32 n = __shfl_up_sync(0xffffffffu, pv, o);
        if (lane >= o) pv += n;
    }
    __syncthreads();                      // protect ws reuse
    if (lane == 31) ws[wid] = pv;
    __syncthreads();
    u32 add = 0;
    #pragma unroll
    for (int w = 0; w < 8; w++) add += (w < wid) ? ws[w] : 0u;
    u32 taken = pv - cnt + add;           // eq elements before my chunk
    u32 byte = 0;
    #pragma unroll
    for (int u = 0; u < 8; u++) {
        u32 k = keys[t * 8 + u];
        bool m = false;
        if (k > T) m = true;
        else if (k == T) { if (taken < remain) m = true; taken++; }
        if (m) byte |= (1u << u);
    }
    atomicOr(&g_colbits[b * NWRD + (t >> 2)], byte << ((t & 3) * 8));
}

// ---------------- fused QKV GEMM (f32x2 core, reg-prefetch pipelined) ----------------
__global__ void __launch_bounds__(256) k_gemmQKV(
        const float* __restrict__ A,
        const float* __restrict__ qw, const float* __restrict__ qb,
        const float* __restrict__ kw, const float* __restrict__ kb,
        const float* __restrict__ vw, const float* __restrict__ vb,
        u32* __restrict__ Qh, u32* __restrict__ Ql,
        u32* __restrict__ Ki, u32* __restrict__ Vi, float qscale) {
    __shared__ __align__(16) u64   As2[16][130];
    __shared__ __align__(16) float Ws[16][68];
    int mode = blockIdx.z;
    const float* W    = (mode == 0) ? qw : (mode == 1) ? kw : vw;
    const float* bias = (mode == 0) ? qb : (mode == 1) ? kb : vb;
    float scale = (mode == 0) ? qscale : 1.0f;

    int tid = threadIdx.x;
    int tx = tid & 15;
    int rg = tid >> 4;
    int m0 = blockIdx.x * 128, c0 = blockIdx.y * 64;
    int lkk = tid & 15, lm = tid >> 4;

    u64 acc[8][2];
    #pragma unroll
    for (int i = 0; i < 8; i++) { acc[i][0] = 0ull; acc[i][1] = 0ull; }

    float a_pre[8], w_pre[4];
    #pragma unroll
    for (int rr = 0; rr < 8; rr++)
        a_pre[rr] = A[(size_t)(m0 + lm + 16 * rr) * DDIM + lkk];
    #pragma unroll
    for (int rr = 0; rr < 4; rr++)
        w_pre[rr] = W[(size_t)(c0 + lm + 16 * rr) * DDIM + lkk];

    for (int k0 = 0; k0 < DDIM; k0 += 16) {
        #pragma unroll
        for (int rr = 0; rr < 8; rr++) As2[lkk][lm + 16 * rr] = pk2(a_pre[rr], a_pre[rr]);
        #pragma unroll
        for (int rr = 0; rr < 4; rr++) Ws[lkk][lm + 16 * rr] = w_pre[rr];
        __syncthreads();
        if (k0 + 16 < DDIM) {
            #pragma unroll
            for (int rr = 0; rr < 8; rr++)
                a_pre[rr] = A[(size_t)(m0 + lm + 16 * rr) * DDIM + k0 + 16 + lkk];
            #pragma unroll
            for (int rr = 0; rr < 4; rr++)
                w_pre[rr] = W[(size_t)(c0 + lm + 16 * rr) * DDIM + k0 + 16 + lkk];
        }
        #pragma unroll
        for (int kk = 0; kk < 16; kk++) {
            float4 w4 = *(const float4*)&Ws[kk][tx * 4];
            u64 w01 = pk2(w4.x, w4.y), w23 = pk2(w4.z, w4.w);
            const u64* arow = &As2[kk][rg * 8];
            #pragma unroll
            for (int ii = 0; ii < 8; ii += 2) {
                ulonglong2 a2 = *(const ulonglong2*)&arow[ii];
                acc[ii][0]     = ffma2(a2.x, w01, acc[ii][0]);
                acc[ii][1]     = ffma2(a2.x, w23, acc[ii][1]);
                acc[ii + 1][0] = ffma2(a2.y, w01, acc[ii + 1][0]);
                acc[ii + 1][1] = ffma2(a2.y, w23, acc[ii + 1][1]);
            }
        }
        __syncthreads();
    }

    float4 b4 = *(const float4*)&bias[c0 + tx * 4];
    int c = c0 + tx * 4;
    int h = (c >> 5) & 7, cw = c & 31;
    int bb = m0 >> 11;
    int n0 = (m0 & 2047) + rg * 8;
    int bh = bb * HH + h;

    if (mode == 2) {
        float vals[8][4];
        #pragma unroll
        for (int ii = 0; ii < 8; ii++) {
            float f0, f1, f2, f3;
            upk2(acc[ii][0], f0, f1);
            upk2(acc[ii][1], f2, f3);
            vals[ii][0] = f0 + b4.x; vals[ii][1] = f1 + b4.y;
            vals[ii][2] = f2 + b4.z; vals[ii][3] = f3 + b4.w;
        }
        int w0v = n0 >> 1;
        int jt = w0v >> 6;
        int s8 = (w0v & 63) >> 3;
        int slot = (w0v >> 2) & 1;
        #pragma unroll
        for (int jj = 0; jj < 4; jj++) {
            int d = cw + jj;
            size_t dbase = ((size_t)bh * HDIM + d) * 2048;
            #pragma unroll
            for (int p = 0; p < 4; p++) {
                float v0 = vals[2*p][jj], v1 = vals[2*p+1][jj];
                float h0 = bf16rt(v0), h1 = bf16rt(v1);
                size_t ub = dbase + (size_t)(jt * 32 + s8 * 4 + p) * 4;
                Vi[ub + slot]     = cvt2(h1, h0);
                Vi[ub + slot + 2] = cvt2(v1 - h1, v0 - h0);
            }
        }
    } else if (mode == 1) {
        int w0 = cw >> 1;
        int kc = w0 >> 3, t0 = w0 & 7;
        int u0 = kc * 4 + (t0 & 3);
        int s = t0 >> 2;
        #pragma unroll
        for (int ii = 0; ii < 8; ii++) {
            float f0, f1, f2, f3;
            upk2(acc[ii][0], f0, f1);
            upk2(acc[ii][1], f2, f3);
            f0 += b4.x; f1 += b4.y; f2 += b4.z; f3 += b4.w;
            float h0 = bf16rt(f0), h1 = bf16rt(f1), h2 = bf16rt(f2), h3 = bf16rt(f3);
            int n = n0 + ii;
            size_t rb = ((size_t)bh * NNODE + n) * 32;
            Ki[rb + u0*4 + s]           = cvt2(h1, h0);
            Ki[rb + (u0+1)*4 + s]       = cvt2(h3, h2);
            Ki[rb + u0*4 + s + 2]       = cvt2(f1 - h1, f0 - h0);
            Ki[rb + (u0+1)*4 + s + 2]   = cvt2(f3 - h3, f2 - h2);
        }
    } else {
        #pragma unroll
        for (int ii = 0; ii < 8; ii++) {
            float f0, f1, f2, f3;
            upk2(acc[ii][0], f0, f1);
            upk2(acc[ii][1], f2, f3);
            f0 = (f0 + b4.x) * scale; f1 = (f1 + b4.y) * scale;
            f2 = (f2 + b4.z) * scale; f3 = (f3 + b4.w) * scale;
            float h0 = bf16rt(f0), h1 = bf16rt(f1), h2 = bf16rt(f2), h3 = bf16rt(f3);
            int n = n0 + ii;
            size_t widx = ((size_t)bh * NNODE + n) * (HDIM/2) + (cw >> 1);
            *(uint2*)&Qh[widx] = make_uint2(cvt2(h1, h0), cvt2(h3, h2));
            *(uint2*)&Ql[widx] = make_uint2(cvt2(f1 - h1, f0 - h0), cvt2(f3 - h3, f2 - h2));
        }
    }
}

// ---------------- fused masked attention + mask writeback ----------------
// cp.async double-buffered K/V/mask staging; dynamic smem (~90KB).
#define KS_U4 1536   // 128*12 uint4 per buffer
#define VS_U4 1152   // 32*36 uint4 per buffer
#define EW_U  512    // 128*4 u32 per buffer
#define ATTN_SMEM (2*KS_U4*16 + 2*VS_U4*16 + 2*EW_U*4 + 16*16)

__device__ __forceinline__ void attn_stage(int buf, int j0, int bh, int b, int i0, int tid,
        uint4* Ks, uint4* Vs, u32* eWp,
        const uint4* gKi, const uint4* gVi, const uint4* gE) {
    uint4* kd = Ks + buf * KS_U4;
    #pragma unroll
    for (int u = 0; u < 8; u++) {
        int idx = tid + u * 128;
        int r = idx >> 3, g = idx & 7;
        cpa16(&kd[r * 12 + g], &gKi[((size_t)bh * NNODE + j0 + r) * 8 + g]);
    }
    uint4* vd = Vs + buf * VS_U4;
    #pragma unroll
    for (int u = 0; u < 8; u++) {
        int idx = tid + u * 128;
        int d = idx >> 5, gv = idx & 31;
        cpa16(&vd[d * 36 + gv], &gVi[((size_t)bh * HDIM + d) * 512 + (j0 >> 7) * 32 + gv]);
    }
    uint4 cb = *(const uint4*)&g_colbits[b * NWRD + (j0 >> 5)];
    uint4 e4 = gE[(size_t)(i0 + tid) * 16 + (j0 >> 7)];
    u32* ew = eWp + buf * EW_U + tid * 4;
    ew[0] = e4.x | cb.x; ew[1] = e4.y | cb.y; ew[2] = e4.z | cb.z; ew[3] = e4.w | cb.w;
}

__global__ void __launch_bounds__(128) k_attn(float* __restrict__ outMask) {
    extern __shared__ __align__(16) char smem[];
    uint4* Ks  = (uint4*)smem;                                  // [2][KS_U4]
    uint4* Vs  = (uint4*)(smem + 2 * KS_U4 * 16);               // [2][VS_U4]
    u32*   eWp = (u32*)  (smem + 2 * KS_U4 * 16 + 2 * VS_U4 * 16);  // [2][EW_U]
    float4* lut = (float4*)(smem + 2 * KS_U4 * 16 + 2 * VS_U4 * 16 + 2 * EW_U * 4);

    int tid = threadIdx.x;
    int wp = tid >> 5, lane = tid & 31;
    int gid = lane >> 2, tig = lane & 3;
    int bh = blockIdx.y, b = bh >> 3, h = bh & 7;
    int i0 = blockIdx.x * 128;

    if (tid < 16) {
        lut[tid] = make_float4((tid & 1) ? 1.0f : 0.0f, (tid & 2) ? 1.0f : 0.0f,
                               (tid & 4) ? 1.0f : 0.0f, (tid & 8) ? 1.0f : 0.0f);
    }

    const u32* gqh = (const u32*)g_Qh;
    const u32* gql = (const u32*)g_Ql;
    const uint4* gKi = (const uint4*)g_Ki;
    const uint4* gVi = (const uint4*)g_Vi;
    const uint4* gE  = (const uint4*)g_edge;

    // stage tile 0
    attn_stage(0, 0, bh, b, i0, tid, Ks, Vs, eWp, gKi, gVi, gE);
    CP_COMMIT();

    u32 qh[2][2][4], ql[2][2][4];
    #pragma unroll
    for (int s = 0; s < 2; s++) {
        size_t blo = ((size_t)bh * NNODE + i0 + s * 64 + wp * 16 + gid) * 16;
        size_t bhi = blo + 8 * 16;
        #pragma unroll
        for (int kc = 0; kc < 2; kc++) {
            qh[s][kc][0] = gqh[blo + kc*8 + tig];
            qh[s][kc][1] = gqh[bhi + kc*8 + tig];
            qh[s][kc][2] = gqh[blo + kc*8 + tig + 4];
            qh[s][kc][3] = gqh[bhi + kc*8 + tig + 4];
            ql[s][kc][0] = gql[blo + kc*8 + tig];
            ql[s][kc][1] = gql[bhi + kc*8 + tig];
            ql[s][kc][2] = gql[blo + kc*8 + tig + 4];
            ql[s][kc][3] = gql[bhi + kc*8 + tig + 4];
        }
    }

    float oc[2][4][4];
    #pragma unroll
    for (int s = 0; s < 2; s++)
        #pragma unroll
        for (int vt = 0; vt < 4; vt++)
            #pragma unroll
            for (int e = 0; e < 4; e++) oc[s][vt][e] = 0.0f;
    float sl[2] = {0.0f, 0.0f}, sh[2] = {0.0f, 0.0f};

    for (int t = 0; t < 16; t++) {
        int cur = t & 1;
        int j0 = t << 7;
        if (t + 1 < 16)
            attn_stage(cur ^ 1, j0 + 128, bh, b, i0, tid, Ks, Vs, eWp, gKi, gVi, gE);
        CP_COMMIT();
        CP_WAIT1();
        __syncthreads();

        const uint4* ksc = Ks + cur * KS_U4;
        const uint4* vsc = Vs + cur * VS_U4;
        const u32*   ewc = eWp + cur * EW_U;

        // coalesced sparse_mask writeback (streaming, LUT nibble expansion)
        {
            int nib = (lane & 7) * 4;
            #pragma unroll 8
            for (int rr = 0; rr < 32; rr++) {
                int r = wp + rr * 4;
                u32 bits = ewc[r * 4 + (lane >> 3)];
                float4 f = lut[(bits >> nib) & 15u];
                __stcs((float4*)(outMask + ((size_t)bh * NNODE + i0 + r) * NNODE + j0) + lane, f);
            }
        }

        #pragma unroll 1
        for (int sub = 0; sub < 4; sub++) {
            float sc[2][4][4];
            #pragma unroll
            for (int s = 0; s < 2; s++)
                #pragma unroll
                for (int nt = 0; nt < 4; nt++)
                    #pragma unroll
                    for (int e = 0; e < 4; e++) sc[s][nt][e] = 0.0f;
            #pragma unroll
            for (int kc = 0; kc < 2; kc++)
                #pragma unroll
                for (int nt = 0; nt < 4; nt++) {
                    int jr = sub * 32 + nt * 8 + gid;
                    uint4 kf = ksc[jr * 12 + kc * 4 + tig];
                    mma16816(sc[0][nt], qh[0][kc], kf.x, kf.y);
                    mma16816(sc[0][nt], ql[0][kc], kf.x, kf.y);
                    mma16816(sc[0][nt], qh[0][kc], kf.z, kf.w);
                    mma16816(sc[1][nt], qh[1][kc], kf.x, kf.y);
                    mma16816(sc[1][nt], ql[1][kc], kf.x, kf.y);
                    mma16816(sc[1][nt], qh[1][kc], kf.z, kf.w);
                }
            u32 ph[2][2][4], pl[2][2][4];
            #pragma unroll
            for (int s = 0; s < 2; s++) {
                u32 wlo = ewc[(s * 64 + wp * 16 + gid) * 4 + sub];
                u32 whi = ewc[(s * 64 + wp * 16 + gid + 8) * 4 + sub];
                float pm[4][4];
                #pragma unroll
                for (int nt = 0; nt < 4; nt++) {
                    float p0 = __expf(sc[s][nt][0]);
                    float p1 = __expf(sc[s][nt][1]);
                    float p2 = __expf(sc[s][nt][2]);
                    float p3 = __expf(sc[s][nt][3]);
                    int bp = nt * 8 + tig * 2;
                    float m0 = ((wlo >> bp) & 1u) ? p0 : 0.0f;
                    float m1 = ((wlo >> (bp + 1)) & 1u) ? p1 : 0.0f;
                    float m2 = ((whi >> bp) & 1u) ? p2 : 0.0f;
                    float m3 = ((whi >> (bp + 1)) & 1u) ? p3 : 0.0f;
                    sl[s] += m0 + m1; sh[s] += m2 + m3;
                    pm[nt][0] = m0; pm[nt][1] = m1; pm[nt][2] = m2; pm[nt][3] = m3;
                }
                #pragma unroll
                for (int kc = 0; kc < 2; kc++) {
                    int na = kc * 2, nb = kc * 2 + 1;
                    float h00 = bf16rt(pm[na][0]), h01 = bf16rt(pm[na][1]);
                    float h02 = bf16rt(pm[na][2]), h03 = bf16rt(pm[na][3]);
                    float h10 = bf16rt(pm[nb][0]), h11 = bf16rt(pm[nb][1]);
                    float h12 = bf16rt(pm[nb][2]), h13 = bf16rt(pm[nb][3]);
                    ph[s][kc][0] = cvt2(h01, h00);
                    ph[s][kc][1] = cvt2(h03, h02);
                    ph[s][kc][2] = cvt2(h11, h10);
                    ph[s][kc][3] = cvt2(h13, h12);
                    pl[s][kc][0] = cvt2(pm[na][1] - h01, pm[na][0] - h00);
                    pl[s][kc][1] = cvt2(pm[na][3] - h03, pm[na][2] - h02);
                    pl[s][kc][2] = cvt2(pm[nb][1] - h11, pm[nb][0] - h10);
                    pl[s][kc][3] = cvt2(pm[nb][3] - h13, pm[nb][2] - h12);
                }
            }
            #pragma unroll
            for (int kc = 0; kc < 2; kc++)
                #pragma unroll
                for (int vt = 0; vt < 4; vt++) {
                    int d = vt * 8 + gid;
                    uint4 vf = vsc[d * 36 + (sub * 2 + kc) * 4 + tig];
                    mma16816(oc[0][vt], ph[0][kc], vf.x, vf.y);
                    mma16816(oc[0][vt], pl[0][kc], vf.x, vf.y);
                    mma16816(oc[0][vt], ph[0][kc], vf.z, vf.w);
                    mma16816(oc[1][vt], ph[1][kc], vf.x, vf.y);
                    mma16816(oc[1][vt], pl[1][kc], vf.x, vf.y);
                    mma16816(oc[1][vt], ph[1][kc], vf.z, vf.w);
                }
        }
        __syncthreads();   // all warps done with buf[cur] before next iter overwrites it
    }

    #pragma unroll
    for (int s = 0; s < 2; s++) {
        float slo = sl[s], shi = sh[s];
        #pragma unroll
        for (int o = 1; o <= 2; o <<= 1) {
            slo += __shfl_xor_sync(0xffffffffu, slo, o);
            shi += __shfl_xor_sync(0xffffffffu, shi, o);
        }
        float invlo = 1.0f / slo;
        float invhi = 1.0f / shi;
        int nlo = i0 + s * 64 + wp * 16 + gid;
        int nhi = nlo + 8;
        size_t olo = ((size_t)(b * NNODE + nlo)) * DDIM + h * HDIM;
        size_t ohi = ((size_t)(b * NNODE + nhi)) * DDIM + h * HDIM;
        #pragma unroll
        for (int vt = 0; vt < 4; vt++) {
            int d = vt * 8 + tig * 2;
            *(float2*)&g_attn[olo + d] = make_float2(oc[s][vt][0] * invlo, oc[s][vt][1] * invlo);
            *(float2*)&g_attn[ohi + d] = make_float2(oc[s][vt][2] * invhi, oc[s][vt][3] * invhi);
        }
    }
}

// ---------------- O projection GEMM: 64x64 tiles, reg-prefetch pipelined ----------------
__global__ void __launch_bounds__(256) k_gemmO(const float* __restrict__ A, const float* __restrict__ W,
                       const float* __restrict__ bias, float* __restrict__ OutF) {
    __shared__ __align__(16) u64   As2[16][66];
    __shared__ __align__(16) float Ws[16][68];
    int tid = threadIdx.x;
    int tx = tid & 15;
    int ty = tid >> 4;
    int m0 = blockIdx.x * 64, c0 = blockIdx.y * 64;
    int lkk = tid & 15, lm = tid >> 4;

    u64 acc[4][2];
    #pragma unroll
    for (int i = 0; i < 4; i++) { acc[i][0] = 0ull; acc[i][1] = 0ull; }

    float a_pre[4], w_pre[4];
    #pragma unroll
    for (int rr = 0; rr < 4; rr++) {
        a_pre[rr] = A[(size_t)(m0 + lm + 16 * rr) * DDIM + lkk];
        w_pre[rr] = W[(size_t)(c0 + lm + 16 * rr) * DDIM + lkk];
    }

    for (int k0 = 0; k0 < DDIM; k0 += 16) {
        #pragma unroll
        for (int rr = 0; rr < 4; rr++) {
            As2[lkk][lm + 16 * rr] = pk2(a_pre[rr], a_pre[rr]);
            Ws[lkk][lm + 16 * rr] = w_pre[rr];
        }
        __syncthreads();
        if (k0 + 16 < DDIM) {
            #pragma unroll
            for (int rr = 0; rr < 4; rr++) {
                a_pre[rr] = A[(size_t)(m0 + lm + 16 * rr) * DDIM + k0 + 16 + lkk];
                w_pre[rr] = W[(size_t)(c0 + lm + 16 * rr) * DDIM + k0 + 16 + lkk];
            }
        }
        #pragma unroll
        for (int kk = 0; kk < 16; kk++) {
            float4 w4 = *(const float4*)&Ws[kk][tx * 4];
            u64 w01 = pk2(w4.x, w4.y), w23 = pk2(w4.z, w4.w);
            const u64* arow = &As2[kk][ty * 4];
            ulonglong2 a01 = *(const ulonglong2*)&arow[0];
            ulonglong2 a23 = *(const ulonglong2*)&arow[2];
            acc[0][0] = ffma2(a01.x, w01, acc[0][0]);
            acc[0][1] = ffma2(a01.x, w23, acc[0][1]);
            acc[1][0] = ffma2(a01.y, w01, acc[1][0]);
            acc[1][1] = ffma2(a01.y, w23, acc[1][1]);
            acc[2][0] = ffma2(a23.x, w01, acc[2][0]);
            acc[2][1] = ffma2(a23.x, w23, acc[2][1]);
            acc[3][0] = ffma2(a23.y, w01, acc[3][0]);
            acc[3][1] = ffma2(a23.y, w23, acc[3][1]);
        }
        __syncthreads();
    }

    float4 b4 = *(const float4*)&bias[c0 + tx * 4];
    int c = c0 + tx * 4;
    #pragma unroll
    for (int ii = 0; ii < 4; ii++) {
        int m = m0 + ty * 4 + ii;
        float f0, f1, f2, f3;
        upk2(acc[ii][0], f0, f1);
        upk2(acc[ii][1], f2, f3);
        *(float4*)&OutF[(size_t)m * DDIM + c] =
            make_float4(f0 + b4.x, f1 + b4.y, f2 + b4.z, f3 + b4.w);
    }
}

// ---------------- launch (single stream; graph-capturable) ----------------
extern "C" void kernel_launch(void* const* d_in, const int* in_sizes, int n_in,
                              void* d_out, int out_size) {
    (void)in_sizes; (void)n_in; (void)out_size;
    const float* x   = (const float*)d_in[0];
    const int*   ei  = (const int*)  d_in[1];
    const float* qw  = (const float*)d_in[2];
    const float* qb  = (const float*)d_in[3];
    const float* kw  = (const float*)d_in[4];
    const float* kb  = (const float*)d_in[5];
    const float* vw  = (const float*)d_in[6];
    const float* vb  = (const float*)d_in[7];
    const float* ow  = (const float*)d_in[8];
    const float* ob  = (const float*)d_in[9];
    const float* g1w = (const float*)d_in[10];
    const float* g1b = (const float*)d_in[11];
    const float* g2w = (const float*)d_in[12];
    const float* g2b = (const float*)d_in[13];

    float* out = (float*)d_out;
    float* outMask = out + (size_t)BB * NNODE * DDIM;

    u32 *pQh, *pQl, *pKi, *pVi;
    float* pAttn;
    cudaGetSymbolAddress((void**)&pQh, g_Qh);
    cudaGetSymbolAddress((void**)&pQl, g_Ql);
    cudaGetSymbolAddress((void**)&pKi, g_Ki);
    cudaGetSymbolAddress((void**)&pVi, g_Vi);
    cudaGetSymbolAddress((void**)&pAttn, g_attn);

    static bool attrSet = false;
    if (!attrSet) {
        cudaFuncSetAttribute(k_attn, cudaFuncAttributeMaxDynamicSharedMemorySize, ATTN_SMEM);
        attrSet = true;
    }

    const float qscale = 0.17677669529663687f;  // 1/sqrt(32)

    k_zero<<<512, 256>>>();
    k_scatter<<<EEDGE / 256, 256>>>(ei);
    k_topo<<<BB * NNODE / 8, 128>>>(x, g1w, g1b, g2w, g2b);
    k_topk<<<BB, 256>>>();

    dim3 qkvgrid(BB * NNODE / 128, DDIM / 64, 3);
    k_gemmQKV<<<qkvgrid, 256>>>(x, qw, qb, kw, kb, vw, vb,
                                pQh, pQl, pKi, pVi, qscale);

    k_attn<<<dim3(NNODE / 128, BB * HH), 128, ATTN_SMEM>>>(outMask);

    k_gemmO<<<dim3(BB * NNODE / 64, DDIM / 64), 256>>>(pAttn, ow, ob, out);
}